// round 7
// baseline (speedup 1.0000x reference)
#include <cuda_runtime.h>
#include <cuda_bf16.h>
#include <stdint.h>
#include <math.h>

#define MAX_N 50000
#define MAX_E 800000
#define DHID 256
#define DIN 512
#define NB_SCAN 128

// Scratch device globals
__device__ int   g_cnt[MAX_N];
__device__ float g_dinv[MAX_N];
__device__ int   g_rowptr[MAX_N + 1];
__device__ int   g_off[MAX_N];
__device__ int   g_blocksum[NB_SCAN];
__device__ int   g_blockoff[NB_SCAN];
__device__ int   g_esrc[MAX_E];
__device__ int   g_edst[MAX_E];
__device__ int   g_eid[MAX_E];
__device__ float g_ecoef[MAX_E];

__device__ __nv_bfloat16 g_xh[(size_t)MAX_N * DIN];
__device__ __nv_bfloat16 g_xl[(size_t)MAX_N * DIN];
__device__ __nv_bfloat16 g_w1h[DIN * DHID];
__device__ __nv_bfloat16 g_w1l[DIN * DHID];
__device__ __nv_bfloat16 g_w2h[DHID * DHID];
__device__ __nv_bfloat16 g_w2l[DHID * DHID];
__device__ float g_h1[(size_t)MAX_N * DHID];
__device__ __nv_bfloat16 g_a1h[(size_t)MAX_N * DHID];
__device__ __nv_bfloat16 g_a1l[(size_t)MAX_N * DHID];
__device__ float g_h2[(size_t)MAX_N * DHID];
__device__ float g_agg2[(size_t)MAX_N * DHID];

// ---------------------------------------------------------------------------
// CSR build
// ---------------------------------------------------------------------------
__global__ void zero_cnt_kernel(int* cnt, int n) {
    int i = blockIdx.x * blockDim.x + threadIdx.x;
    if (i < n) cnt[i] = 0;
}

__global__ void hist_kernel(int* cnt, const int* __restrict__ dst, int e) {
    int i = blockIdx.x * blockDim.x + threadIdx.x;
    if (i < e) atomicAdd(&cnt[dst[i]], 1);
}

__global__ void dinv_kernel(const int* __restrict__ cnt, float* __restrict__ dinv, int n) {
    int i = blockIdx.x * blockDim.x + threadIdx.x;
    if (i < n) dinv[i] = rsqrtf((float)(cnt[i] + 1));
}

__global__ __launch_bounds__(256)
void scan_p1_kernel(const int* __restrict__ cnt, int* __restrict__ blocksum, int n) {
    __shared__ int red[256];
    const int chunk = (n + NB_SCAN - 1) / NB_SCAN;
    const int beg = blockIdx.x * chunk;
    const int end = min(beg + chunk, n);
    int s = 0;
    for (int i = beg + threadIdx.x; i < end; i += 256) s += cnt[i];
    red[threadIdx.x] = s;
    __syncthreads();
    for (int d = 128; d > 0; d >>= 1) {
        if (threadIdx.x < d) red[threadIdx.x] += red[threadIdx.x + d];
        __syncthreads();
    }
    if (threadIdx.x == 0) blocksum[blockIdx.x] = red[0];
}

__global__ __launch_bounds__(NB_SCAN)
void scan_p2_kernel(const int* __restrict__ blocksum, int* __restrict__ blockoff,
                    int* __restrict__ rowptr, int n) {
    __shared__ int sh[NB_SCAN];
    const int t = threadIdx.x;
    sh[t] = blocksum[t];
    __syncthreads();
    for (int d = 1; d < NB_SCAN; d <<= 1) {
        int v = (t >= d) ? sh[t - d] : 0;
        __syncthreads();
        sh[t] += v;
        __syncthreads();
    }
    blockoff[t] = (t == 0) ? 0 : sh[t - 1];
    if (t == NB_SCAN - 1) rowptr[n] = sh[NB_SCAN - 1];
}

__global__ __launch_bounds__(256)
void scan_p3_kernel(const int* __restrict__ cnt, const int* __restrict__ blockoff,
                    int* __restrict__ rowptr, int* __restrict__ off, int n) {
    __shared__ int sh[256];
    const int chunk = (n + NB_SCAN - 1) / NB_SCAN;
    const int beg = blockIdx.x * chunk;
    const int end = min(beg + chunk, n);
    int running = blockoff[blockIdx.x];
    for (int base = beg; base < end; base += 256) {
        const int i = base + threadIdx.x;
        int v = (i < end) ? cnt[i] : 0;
        sh[threadIdx.x] = v;
        __syncthreads();
        for (int d = 1; d < 256; d <<= 1) {
            int t2 = (threadIdx.x >= d) ? sh[threadIdx.x - d] : 0;
            __syncthreads();
            sh[threadIdx.x] += t2;
            __syncthreads();
        }
        if (i < end) {
            const int excl = sh[threadIdx.x] - v;
            rowptr[i] = running + excl;
            off[i] = running + excl;
        }
        running += sh[255];
        __syncthreads();
    }
}

__global__ void scatter_kernel(const int* __restrict__ src, const int* __restrict__ dst,
                               const float* __restrict__ dinv, int* __restrict__ off,
                               int* __restrict__ esrc, int* __restrict__ edst,
                               int* __restrict__ eid, float* __restrict__ ecoef, int e) {
    int i = blockIdx.x * blockDim.x + threadIdx.x;
    if (i < e) {
        const int s = src[i];
        const int d = dst[i];
        const int pos = atomicAdd(&off[d], 1);
        esrc[pos] = s;
        edst[pos] = d;
        eid[pos] = i;
        ecoef[pos] = dinv[s] * dinv[d];
    }
}

// ---------------------------------------------------------------------------
// fp32 -> (hi, lo) bf16 split, elementwise (for x, W1, W2)
// ---------------------------------------------------------------------------
__global__ void split_kernel(const float* __restrict__ in,
                             __nv_bfloat16* __restrict__ hi,
                             __nv_bfloat16* __restrict__ lo, int n4) {
    int i = blockIdx.x * blockDim.x + threadIdx.x;
    if (i >= n4) return;
    float4 v = reinterpret_cast<const float4*>(in)[i];
    __nv_bfloat16 h0 = __float2bfloat16(v.x);
    __nv_bfloat16 h1 = __float2bfloat16(v.y);
    __nv_bfloat16 h2 = __float2bfloat16(v.z);
    __nv_bfloat16 h3 = __float2bfloat16(v.w);
    __nv_bfloat16 l0 = __float2bfloat16(v.x - __bfloat162float(h0));
    __nv_bfloat16 l1 = __float2bfloat16(v.y - __bfloat162float(h1));
    __nv_bfloat16 l2 = __float2bfloat16(v.z - __bfloat162float(h2));
    __nv_bfloat16 l3 = __float2bfloat16(v.w - __bfloat162float(h3));
    hi[i * 4 + 0] = h0; hi[i * 4 + 1] = h1; hi[i * 4 + 2] = h2; hi[i * 4 + 3] = h3;
    lo[i * 4 + 0] = l0; lo[i * 4 + 1] = l1; lo[i * 4 + 2] = l2; lo[i * 4 + 3] = l3;
}

// ---------------------------------------------------------------------------
// Tensor-core GEMM on pre-split bf16 operands.
// C[M,N] = (Ah+Al)[M,K] @ (Bh+Bl)[K,N]; fp32 accum; 3-term compensation.
// CTA tile 128x128, BK=16, 8 warps (4m x 2n), warp tile 32x64, cp.async 2-stage.
// ---------------------------------------------------------------------------
#define A_PAD 24   // 16 data + 8 pad -> 48B row stride (conflict-free ldsm)
#define B_PAD 136  // 128 data + 8 pad -> 272B row stride (conflict-free ldsm)

__device__ __forceinline__ void ldsm_x4(uint32_t addr, uint32_t& r0, uint32_t& r1,
                                        uint32_t& r2, uint32_t& r3) {
    asm volatile("ldmatrix.sync.aligned.m8n8.x4.shared.b16 {%0,%1,%2,%3}, [%4];"
                 : "=r"(r0), "=r"(r1), "=r"(r2), "=r"(r3) : "r"(addr));
}
__device__ __forceinline__ void ldsm_x4_t(uint32_t addr, uint32_t& r0, uint32_t& r1,
                                          uint32_t& r2, uint32_t& r3) {
    asm volatile("ldmatrix.sync.aligned.m8n8.x4.trans.shared.b16 {%0,%1,%2,%3}, [%4];"
                 : "=r"(r0), "=r"(r1), "=r"(r2), "=r"(r3) : "r"(addr));
}
__device__ __forceinline__ void mma_bf16(float* d, const uint32_t* a, const uint32_t* b) {
    asm volatile("mma.sync.aligned.m16n8k16.row.col.f32.bf16.bf16.f32 "
                 "{%0,%1,%2,%3}, {%4,%5,%6,%7}, {%8,%9}, {%0,%1,%2,%3};"
                 : "+f"(d[0]), "+f"(d[1]), "+f"(d[2]), "+f"(d[3])
                 : "r"(a[0]), "r"(a[1]), "r"(a[2]), "r"(a[3]), "r"(b[0]), "r"(b[1]));
}
__device__ __forceinline__ void cp_async16(void* smem_dst, const void* gsrc, bool pred) {
    uint32_t saddr = (uint32_t)__cvta_generic_to_shared(smem_dst);
    int sz = pred ? 16 : 0;
    asm volatile("cp.async.cg.shared.global [%0], [%1], 16, %2;"
                 :: "r"(saddr), "l"(gsrc), "r"(sz));
}

__global__ __launch_bounds__(256)
void mma_gemm_pre_kernel(const __nv_bfloat16* __restrict__ Ahg,
                         const __nv_bfloat16* __restrict__ Alg,
                         const __nv_bfloat16* __restrict__ Bhg,
                         const __nv_bfloat16* __restrict__ Blg,
                         float* __restrict__ C, int M, int K, int N) {
    __shared__ __nv_bfloat16 Ah[2][128][A_PAD];
    __shared__ __nv_bfloat16 Al[2][128][A_PAD];
    __shared__ __nv_bfloat16 Bh[2][16][B_PAD];
    __shared__ __nv_bfloat16 Bl[2][16][B_PAD];

    const int tid = threadIdx.x;
    const int wid = tid >> 5;
    const int lane = tid & 31;
    const int warp_m = wid & 3;      // 0..3 -> 32-row slice
    const int warp_n = wid >> 2;     // 0..1 -> 64-col slice
    const int rowBase = blockIdx.y * 128;
    const int colBase = blockIdx.x * 128;

    // A staging: 128 rows x 16 k; thread -> one 8-elem chunk for Ah and Al
    const int a_r = tid >> 1;
    const int a_k = (tid & 1) << 3;
    const int arow = rowBase + a_r;
    const bool a_ok = (arow < M);
    // B staging: 16 rows x 128 cols; thread -> one 8-elem chunk for Bh and Bl
    const int b_r = tid >> 4;          // 0..15
    const int b_c = (tid & 15) << 3;   // 0..120

    const int lrow = lane & 7;
    const int lmat = lane >> 3;
    const int a_mloc = ((lmat & 1) << 3) + lrow;
    const int a_khalf = lmat >> 1;
    const int b_krow = ((lmat & 1) << 3) + lrow;
    const int b_nhalf = lmat >> 1;

    float acc[2][8][4];
#pragma unroll
    for (int i = 0; i < 2; i++)
#pragma unroll
        for (int j = 0; j < 8; j++)
#pragma unroll
            for (int q = 0; q < 4; q++) acc[i][j][q] = 0.0f;

    const int KT = K >> 4;

    {
        cp_async16(&Ah[0][a_r][a_k], Ahg + (size_t)arow * K + a_k, a_ok);
        cp_async16(&Al[0][a_r][a_k], Alg + (size_t)arow * K + a_k, a_ok);
        cp_async16(&Bh[0][b_r][b_c], Bhg + (size_t)b_r * N + colBase + b_c, true);
        cp_async16(&Bl[0][b_r][b_c], Blg + (size_t)b_r * N + colBase + b_c, true);
        asm volatile("cp.async.commit_group;");
    }

    int buf = 0;
    for (int kt = 0; kt < KT; kt++) {
        asm volatile("cp.async.wait_group 0;");
        __syncthreads();

        if (kt + 1 < KT) {
            const int k0 = (kt + 1) << 4;
            const int nb = buf ^ 1;
            cp_async16(&Ah[nb][a_r][a_k], Ahg + (size_t)arow * K + k0 + a_k, a_ok);
            cp_async16(&Al[nb][a_r][a_k], Alg + (size_t)arow * K + k0 + a_k, a_ok);
            cp_async16(&Bh[nb][b_r][b_c], Bhg + (size_t)(k0 + b_r) * N + colBase + b_c, true);
            cp_async16(&Bl[nb][b_r][b_c], Blg + (size_t)(k0 + b_r) * N + colBase + b_c, true);
            asm volatile("cp.async.commit_group;");
        }

        uint32_t ah[2][4], al[2][4];
#pragma unroll
        for (int mf = 0; mf < 2; mf++) {
            const int m_base = warp_m * 32 + mf * 16;
            uint32_t addr_h = (uint32_t)__cvta_generic_to_shared(
                &Ah[buf][m_base + a_mloc][a_khalf * 8]);
            ldsm_x4(addr_h, ah[mf][0], ah[mf][1], ah[mf][2], ah[mf][3]);
            uint32_t addr_l = (uint32_t)__cvta_generic_to_shared(
                &Al[buf][m_base + a_mloc][a_khalf * 8]);
            ldsm_x4(addr_l, al[mf][0], al[mf][1], al[mf][2], al[mf][3]);
        }
        uint32_t bh[4][4], bl[4][4];
#pragma unroll
        for (int g = 0; g < 4; g++) {
            const int n_base = warp_n * 64 + g * 16;
            uint32_t addr_h = (uint32_t)__cvta_generic_to_shared(
                &Bh[buf][b_krow][n_base + b_nhalf * 8]);
            ldsm_x4_t(addr_h, bh[g][0], bh[g][1], bh[g][2], bh[g][3]);
            uint32_t addr_l = (uint32_t)__cvta_generic_to_shared(
                &Bl[buf][b_krow][n_base + b_nhalf * 8]);
            ldsm_x4_t(addr_l, bl[g][0], bl[g][1], bl[g][2], bl[g][3]);
        }
#pragma unroll
        for (int mf = 0; mf < 2; mf++) {
#pragma unroll
            for (int g = 0; g < 4; g++) {
#pragma unroll
                for (int h = 0; h < 2; h++) {
                    float* d = acc[mf][g * 2 + h];
                    const uint32_t bhp[2] = {bh[g][h * 2], bh[g][h * 2 + 1]};
                    const uint32_t blp[2] = {bl[g][h * 2], bl[g][h * 2 + 1]};
                    mma_bf16(d, ah[mf], bhp);
                    mma_bf16(d, ah[mf], blp);
                    mma_bf16(d, al[mf], bhp);
                }
            }
        }
        buf ^= 1;
    }

    const int lq = lane >> 2;
    const int lr = lane & 3;
#pragma unroll
    for (int mf = 0; mf < 2; mf++) {
#pragma unroll
        for (int g = 0; g < 4; g++) {
#pragma unroll
            for (int h = 0; h < 2; h++) {
                const float* d = acc[mf][g * 2 + h];
                const int col = colBase + warp_n * 64 + g * 16 + h * 8 + lr * 2;
                const int r0 = rowBase + warp_m * 32 + mf * 16 + lq;
                if (r0 < M)
                    *reinterpret_cast<float2*>(C + (size_t)r0 * N + col) =
                        make_float2(d[0], d[1]);
                const int r1 = r0 + 8;
                if (r1 < M)
                    *reinterpret_cast<float2*>(C + (size_t)r1 * N + col) =
                        make_float2(d[2], d[3]);
            }
        }
    }
}

// ---------------------------------------------------------------------------
// CSR aggregation. MODE 0: write fp32. MODE 1: relu + bf16 split write.
// ---------------------------------------------------------------------------
template <int MODE>
__global__ __launch_bounds__(256)
void agg_csr_kernel(const float* __restrict__ h, const float* __restrict__ bias,
                    const float* __restrict__ dinv,
                    const int* __restrict__ rowptr, const int* __restrict__ esrc,
                    const float* __restrict__ ecoef,
                    float* __restrict__ outf,
                    __nv_bfloat16* __restrict__ outh,
                    __nv_bfloat16* __restrict__ outl, int n) {
    const int node = blockIdx.x * 4 + (threadIdx.x >> 6);
    if (node >= n) return;
    const int c = (threadIdx.x & 63) << 2;

    const float di = dinv[node];
    const float wself = di * di;
    float4 hv = *reinterpret_cast<const float4*>(h + (size_t)node * DHID + c);
    float4 bb = *reinterpret_cast<const float4*>(bias + c);
    float4 acc;
    acc.x = fmaf(hv.x, wself, bb.x);
    acc.y = fmaf(hv.y, wself, bb.y);
    acc.z = fmaf(hv.z, wself, bb.z);
    acc.w = fmaf(hv.w, wself, bb.w);

    const int beg = rowptr[node];
    const int end = rowptr[node + 1];
    int e = beg;
    for (; e + 2 <= end; e += 2) {
        const int s0 = esrc[e];
        const int s1 = esrc[e + 1];
        const float c0 = ecoef[e];
        const float c1 = ecoef[e + 1];
        float4 v0 = *reinterpret_cast<const float4*>(h + (size_t)s0 * DHID + c);
        float4 v1 = *reinterpret_cast<const float4*>(h + (size_t)s1 * DHID + c);
        acc.x += c0 * v0.x + c1 * v1.x;
        acc.y += c0 * v0.y + c1 * v1.y;
        acc.z += c0 * v0.z + c1 * v1.z;
        acc.w += c0 * v0.w + c1 * v1.w;
    }
    if (e < end) {
        const int s0 = esrc[e];
        const float c0 = ecoef[e];
        float4 v0 = *reinterpret_cast<const float4*>(h + (size_t)s0 * DHID + c);
        acc.x += c0 * v0.x;
        acc.y += c0 * v0.y;
        acc.z += c0 * v0.z;
        acc.w += c0 * v0.w;
    }

    if (MODE == 0) {
        *reinterpret_cast<float4*>(outf + (size_t)node * DHID + c) = acc;
    } else {
        float v0 = fmaxf(acc.x, 0.f), v1 = fmaxf(acc.y, 0.f);
        float v2 = fmaxf(acc.z, 0.f), v3 = fmaxf(acc.w, 0.f);
        __nv_bfloat16 h0 = __float2bfloat16(v0);
        __nv_bfloat16 h1 = __float2bfloat16(v1);
        __nv_bfloat16 h2 = __float2bfloat16(v2);
        __nv_bfloat16 h3 = __float2bfloat16(v3);
        __nv_bfloat16 l0 = __float2bfloat16(v0 - __bfloat162float(h0));
        __nv_bfloat16 l1 = __float2bfloat16(v1 - __bfloat162float(h1));
        __nv_bfloat16 l2 = __float2bfloat16(v2 - __bfloat162float(h2));
        __nv_bfloat16 l3 = __float2bfloat16(v3 - __bfloat162float(h3));
        __nv_bfloat16* ph = outh + (size_t)node * DHID + c;
        __nv_bfloat16* pl = outl + (size_t)node * DHID + c;
        ph[0] = h0; ph[1] = h1; ph[2] = h2; ph[3] = h3;
        pl[0] = l0; pl[1] = l1; pl[2] = l2; pl[3] = l3;
    }
}

// ---------------------------------------------------------------------------
// Edge scoring over the CSR-ORDERED edge list (edge-parallel, one warp/slot).
// Consecutive slots share dst -> dst row hits L1. out[eid[e]] scatters result.
// ---------------------------------------------------------------------------
__global__ __launch_bounds__(256)
void score_csr_edge_kernel(const float* __restrict__ h,
                           const int* __restrict__ esrc,
                           const int* __restrict__ edst,
                           const int* __restrict__ eid,
                           float* __restrict__ out, int e) {
    unsigned gt = blockIdx.x * blockDim.x + threadIdx.x;
    unsigned ed = gt >> 5;
    const int lane = threadIdx.x & 31;
    if (ed >= (unsigned)e) return;
    const int s = esrc[ed];
    const int d = edst[ed];
    const float4* ps = reinterpret_cast<const float4*>(h + (size_t)s * DHID) + lane * 2;
    const float4* pd = reinterpret_cast<const float4*>(h + (size_t)d * DHID) + lane * 2;
    float4 a0 = ps[0], a1 = ps[1];
    float4 b0 = pd[0], b1 = pd[1];
    float acc = a0.x * b0.x + a0.y * b0.y + a0.z * b0.z + a0.w * b0.w;
    acc += a1.x * b1.x + a1.y * b1.y + a1.z * b1.z + a1.w * b1.w;
#pragma unroll
    for (int off = 16; off > 0; off >>= 1)
        acc += __shfl_xor_sync(0xFFFFFFFFu, acc, off);
    if (lane == 0) out[eid[ed]] = 1.0f / (1.0f + expf(-acc));
}

// ---------------------------------------------------------------------------
// Host launcher
// ---------------------------------------------------------------------------
extern "C" void kernel_launch(void* const* d_in, const int* in_sizes, int n_in,
                              void* d_out, int out_size) {
    const float* x  = (const float*)d_in[0];
    const int*   ei = (const int*)d_in[1];
    const float* W1 = (const float*)d_in[2];
    const float* b1 = (const float*)d_in[3];
    const float* W2 = (const float*)d_in[4];
    const float* b2 = (const float*)d_in[5];
    float* out = (float*)d_out;

    const int N = in_sizes[0] / DIN;
    const int E = in_sizes[1] / 2;
    const int* src = ei;
    const int* dst = ei + E;

    int *p_cnt, *p_rowptr, *p_off, *p_esrc, *p_edst, *p_eid, *p_bsum, *p_boff;
    float *p_dinv, *p_ecoef, *p_h1, *p_h2, *p_agg2;
    __nv_bfloat16 *p_xh, *p_xl, *p_w1h, *p_w1l, *p_w2h, *p_w2l, *p_a1h, *p_a1l;
    cudaGetSymbolAddress((void**)&p_cnt,    g_cnt);
    cudaGetSymbolAddress((void**)&p_dinv,   g_dinv);
    cudaGetSymbolAddress((void**)&p_rowptr, g_rowptr);
    cudaGetSymbolAddress((void**)&p_off,    g_off);
    cudaGetSymbolAddress((void**)&p_bsum,   g_blocksum);
    cudaGetSymbolAddress((void**)&p_boff,   g_blockoff);
    cudaGetSymbolAddress((void**)&p_esrc,   g_esrc);
    cudaGetSymbolAddress((void**)&p_edst,   g_edst);
    cudaGetSymbolAddress((void**)&p_eid,    g_eid);
    cudaGetSymbolAddress((void**)&p_ecoef,  g_ecoef);
    cudaGetSymbolAddress((void**)&p_xh,     g_xh);
    cudaGetSymbolAddress((void**)&p_xl,     g_xl);
    cudaGetSymbolAddress((void**)&p_w1h,    g_w1h);
    cudaGetSymbolAddress((void**)&p_w1l,    g_w1l);
    cudaGetSymbolAddress((void**)&p_w2h,    g_w2h);
    cudaGetSymbolAddress((void**)&p_w2l,    g_w2l);
    cudaGetSymbolAddress((void**)&p_h1,     g_h1);
    cudaGetSymbolAddress((void**)&p_a1h,    g_a1h);
    cudaGetSymbolAddress((void**)&p_a1l,    g_a1l);
    cudaGetSymbolAddress((void**)&p_h2,     g_h2);
    cudaGetSymbolAddress((void**)&p_agg2,   g_agg2);

    const int T = 256;

    // 1) CSR build + normalization
    zero_cnt_kernel<<<(N + T - 1) / T, T>>>(p_cnt, N);
    hist_kernel<<<(E + T - 1) / T, T>>>(p_cnt, dst, E);
    dinv_kernel<<<(N + T - 1) / T, T>>>(p_cnt, p_dinv, N);
    scan_p1_kernel<<<NB_SCAN, 256>>>(p_cnt, p_bsum, N);
    scan_p2_kernel<<<1, NB_SCAN>>>(p_bsum, p_boff, p_rowptr, N);
    scan_p3_kernel<<<NB_SCAN, 256>>>(p_cnt, p_boff, p_rowptr, p_off, N);
    scatter_kernel<<<(E + T - 1) / T, T>>>(src, dst, p_dinv, p_off,
                                           p_esrc, p_edst, p_eid, p_ecoef, E);

    // 2) pre-split operands to bf16 (hi, lo)
    {
        int n4 = N * DIN / 4;
        split_kernel<<<(n4 + T - 1) / T, T>>>(x, p_xh, p_xl, n4);
        int w1n4 = DIN * DHID / 4;
        split_kernel<<<(w1n4 + T - 1) / T, T>>>(W1, p_w1h, p_w1l, w1n4);
        int w2n4 = DHID * DHID / 4;
        split_kernel<<<(w2n4 + T - 1) / T, T>>>(W2, p_w2h, p_w2l, w2n4);
    }

    // 3) layer 1: h1 = x @ W1 ; agg1 -> relu + split
    {
        dim3 grid(DHID / 128, (N + 127) / 128);
        mma_gemm_pre_kernel<<<grid, 256>>>(p_xh, p_xl, p_w1h, p_w1l, p_h1, N, DIN, DHID);
    }
    agg_csr_kernel<1><<<(N + 3) / 4, 256>>>(p_h1, b1, p_dinv, p_rowptr, p_esrc, p_ecoef,
                                            nullptr, p_a1h, p_a1l, N);

    // 4) layer 2: h2 = relu(agg1) @ W2 ; agg2 fp32
    {
        dim3 grid(DHID / 128, (N + 127) / 128);
        mma_gemm_pre_kernel<<<grid, 256>>>(p_a1h, p_a1l, p_w2h, p_w2l, p_h2, N, DHID, DHID);
    }
    agg_csr_kernel<0><<<(N + 3) / 4, 256>>>(p_h2, b2, p_dinv, p_rowptr, p_esrc, p_ecoef,
                                            p_agg2, nullptr, nullptr, N);

    // 5) edge scoring over CSR-ordered list (dst-row L1 reuse)
    score_csr_edge_kernel<<<((unsigned)E * 32 + T - 1) / T, T>>>(p_agg2, p_esrc, p_edst,
                                                                 p_eid, out, E);
}

// round 8
// speedup vs baseline: 1.1470x; 1.1470x over previous
#include <cuda_runtime.h>
#include <cuda_bf16.h>
#include <stdint.h>
#include <math.h>

#define MAX_N 50000
#define MAX_E 800000
#define DHID 256
#define DIN 512
#define NB_SCAN 128

// Scratch device globals
__device__ int   g_cnt[MAX_N];
__device__ float g_dinv[MAX_N];
__device__ int   g_rowptr[MAX_N + 1];
__device__ int   g_off[MAX_N];
__device__ int   g_blocksum[NB_SCAN];
__device__ int   g_blockoff[NB_SCAN];
__device__ int   g_esrc[MAX_E];
__device__ float g_ecoef[MAX_E];

__device__ __nv_bfloat16 g_xh[(size_t)MAX_N * DIN];
__device__ __nv_bfloat16 g_xl[(size_t)MAX_N * DIN];
__device__ __nv_bfloat16 g_w1h[DIN * DHID];
__device__ __nv_bfloat16 g_w1l[DIN * DHID];
__device__ __nv_bfloat16 g_w2h[DHID * DHID];
__device__ __nv_bfloat16 g_w2l[DHID * DHID];
__device__ float g_h1[(size_t)MAX_N * DHID];
__device__ __nv_bfloat16 g_a1h[(size_t)MAX_N * DHID];
__device__ __nv_bfloat16 g_a1l[(size_t)MAX_N * DHID];
__device__ float g_h2[(size_t)MAX_N * DHID];
__device__ float g_agg2[(size_t)MAX_N * DHID];

// ---------------------------------------------------------------------------
// CSR build
// ---------------------------------------------------------------------------
__global__ void zero_cnt_kernel(int* cnt, int n) {
    int i = blockIdx.x * blockDim.x + threadIdx.x;
    if (i < n) cnt[i] = 0;
}

__global__ void hist_kernel(int* cnt, const int* __restrict__ dst, int e) {
    int i = blockIdx.x * blockDim.x + threadIdx.x;
    if (i < e) atomicAdd(&cnt[dst[i]], 1);
}

__global__ void dinv_kernel(const int* __restrict__ cnt, float* __restrict__ dinv, int n) {
    int i = blockIdx.x * blockDim.x + threadIdx.x;
    if (i < n) dinv[i] = rsqrtf((float)(cnt[i] + 1));
}

__global__ __launch_bounds__(256)
void scan_p1_kernel(const int* __restrict__ cnt, int* __restrict__ blocksum, int n) {
    __shared__ int red[256];
    const int chunk = (n + NB_SCAN - 1) / NB_SCAN;
    const int beg = blockIdx.x * chunk;
    const int end = min(beg + chunk, n);
    int s = 0;
    for (int i = beg + threadIdx.x; i < end; i += 256) s += cnt[i];
    red[threadIdx.x] = s;
    __syncthreads();
    for (int d = 128; d > 0; d >>= 1) {
        if (threadIdx.x < d) red[threadIdx.x] += red[threadIdx.x + d];
        __syncthreads();
    }
    if (threadIdx.x == 0) blocksum[blockIdx.x] = red[0];
}

__global__ __launch_bounds__(NB_SCAN)
void scan_p2_kernel(const int* __restrict__ blocksum, int* __restrict__ blockoff,
                    int* __restrict__ rowptr, int n) {
    __shared__ int sh[NB_SCAN];
    const int t = threadIdx.x;
    sh[t] = blocksum[t];
    __syncthreads();
    for (int d = 1; d < NB_SCAN; d <<= 1) {
        int v = (t >= d) ? sh[t - d] : 0;
        __syncthreads();
        sh[t] += v;
        __syncthreads();
    }
    blockoff[t] = (t == 0) ? 0 : sh[t - 1];
    if (t == NB_SCAN - 1) rowptr[n] = sh[NB_SCAN - 1];
}

__global__ __launch_bounds__(256)
void scan_p3_kernel(const int* __restrict__ cnt, const int* __restrict__ blockoff,
                    int* __restrict__ rowptr, int* __restrict__ off, int n) {
    __shared__ int sh[256];
    const int chunk = (n + NB_SCAN - 1) / NB_SCAN;
    const int beg = blockIdx.x * chunk;
    const int end = min(beg + chunk, n);
    int running = blockoff[blockIdx.x];
    for (int base = beg; base < end; base += 256) {
        const int i = base + threadIdx.x;
        int v = (i < end) ? cnt[i] : 0;
        sh[threadIdx.x] = v;
        __syncthreads();
        for (int d = 1; d < 256; d <<= 1) {
            int t2 = (threadIdx.x >= d) ? sh[threadIdx.x - d] : 0;
            __syncthreads();
            sh[threadIdx.x] += t2;
            __syncthreads();
        }
        if (i < end) {
            const int excl = sh[threadIdx.x] - v;
            rowptr[i] = running + excl;
            off[i] = running + excl;
        }
        running += sh[255];
        __syncthreads();
    }
}

__global__ void scatter_kernel(const int* __restrict__ src, const int* __restrict__ dst,
                               const float* __restrict__ dinv, int* __restrict__ off,
                               int* __restrict__ esrc, float* __restrict__ ecoef, int e) {
    int i = blockIdx.x * blockDim.x + threadIdx.x;
    if (i < e) {
        const int s = src[i];
        const int d = dst[i];
        const int pos = atomicAdd(&off[d], 1);
        esrc[pos] = s;
        ecoef[pos] = dinv[s] * dinv[d];
    }
}

// ---------------------------------------------------------------------------
// fp32 -> (hi, lo) bf16 split
// ---------------------------------------------------------------------------
__global__ void split_kernel(const float* __restrict__ in,
                             __nv_bfloat16* __restrict__ hi,
                             __nv_bfloat16* __restrict__ lo, int n4) {
    int i = blockIdx.x * blockDim.x + threadIdx.x;
    if (i >= n4) return;
    float4 v = reinterpret_cast<const float4*>(in)[i];
    __nv_bfloat16 h0 = __float2bfloat16(v.x);
    __nv_bfloat16 h1 = __float2bfloat16(v.y);
    __nv_bfloat16 h2 = __float2bfloat16(v.z);
    __nv_bfloat16 h3 = __float2bfloat16(v.w);
    __nv_bfloat16 l0 = __float2bfloat16(v.x - __bfloat162float(h0));
    __nv_bfloat16 l1 = __float2bfloat16(v.y - __bfloat162float(h1));
    __nv_bfloat16 l2 = __float2bfloat16(v.z - __bfloat162float(h2));
    __nv_bfloat16 l3 = __float2bfloat16(v.w - __bfloat162float(h3));
    hi[i * 4 + 0] = h0; hi[i * 4 + 1] = h1; hi[i * 4 + 2] = h2; hi[i * 4 + 3] = h3;
    lo[i * 4 + 0] = l0; lo[i * 4 + 1] = l1; lo[i * 4 + 2] = l2; lo[i * 4 + 3] = l3;
}

// ---------------------------------------------------------------------------
// Tensor-core GEMM on pre-split bf16 operands (R6 config: CTA 128x64, BK=16).
// ---------------------------------------------------------------------------
#define A_PAD 24
#define B_PAD 72

__device__ __forceinline__ void ldsm_x4(uint32_t addr, uint32_t& r0, uint32_t& r1,
                                        uint32_t& r2, uint32_t& r3) {
    asm volatile("ldmatrix.sync.aligned.m8n8.x4.shared.b16 {%0,%1,%2,%3}, [%4];"
                 : "=r"(r0), "=r"(r1), "=r"(r2), "=r"(r3) : "r"(addr));
}
__device__ __forceinline__ void ldsm_x4_t(uint32_t addr, uint32_t& r0, uint32_t& r1,
                                          uint32_t& r2, uint32_t& r3) {
    asm volatile("ldmatrix.sync.aligned.m8n8.x4.trans.shared.b16 {%0,%1,%2,%3}, [%4];"
                 : "=r"(r0), "=r"(r1), "=r"(r2), "=r"(r3) : "r"(addr));
}
__device__ __forceinline__ void mma_bf16(float* d, const uint32_t* a, const uint32_t* b) {
    asm volatile("mma.sync.aligned.m16n8k16.row.col.f32.bf16.bf16.f32 "
                 "{%0,%1,%2,%3}, {%4,%5,%6,%7}, {%8,%9}, {%0,%1,%2,%3};"
                 : "+f"(d[0]), "+f"(d[1]), "+f"(d[2]), "+f"(d[3])
                 : "r"(a[0]), "r"(a[1]), "r"(a[2]), "r"(a[3]), "r"(b[0]), "r"(b[1]));
}
__device__ __forceinline__ void cp_async16(void* smem_dst, const void* gsrc, bool pred) {
    uint32_t saddr = (uint32_t)__cvta_generic_to_shared(smem_dst);
    int sz = pred ? 16 : 0;
    asm volatile("cp.async.cg.shared.global [%0], [%1], 16, %2;"
                 :: "r"(saddr), "l"(gsrc), "r"(sz));
}

__global__ __launch_bounds__(256)
void mma_gemm_pre_kernel(const __nv_bfloat16* __restrict__ Ahg,
                         const __nv_bfloat16* __restrict__ Alg,
                         const __nv_bfloat16* __restrict__ Bhg,
                         const __nv_bfloat16* __restrict__ Blg,
                         float* __restrict__ C, int M, int K, int N) {
    __shared__ __nv_bfloat16 Ah[2][128][A_PAD];
    __shared__ __nv_bfloat16 Al[2][128][A_PAD];
    __shared__ __nv_bfloat16 Bh[2][16][B_PAD];
    __shared__ __nv_bfloat16 Bl[2][16][B_PAD];

    const int tid = threadIdx.x;
    const int wid = tid >> 5;
    const int lane = tid & 31;
    const int warp_m = wid & 3;
    const int warp_n = wid >> 2;
    const int rowBase = blockIdx.y * 128;
    const int colBase = blockIdx.x * 64;

    const int a_r = tid >> 1;
    const int a_k = (tid & 1) << 3;
    const int arow = rowBase + a_r;
    const bool a_ok = (arow < M);
    const int bt = tid & 127;
    const int b_r = bt >> 3;
    const int b_c = (bt & 7) << 3;
    const bool is_bh = (tid < 128);

    const int lrow = lane & 7;
    const int lmat = lane >> 3;
    const int a_mloc = ((lmat & 1) << 3) + lrow;
    const int a_khalf = lmat >> 1;
    const int b_krow = ((lmat & 1) << 3) + lrow;
    const int b_nhalf = lmat >> 1;

    float acc[2][4][4];
#pragma unroll
    for (int i = 0; i < 2; i++)
#pragma unroll
        for (int j = 0; j < 4; j++)
#pragma unroll
            for (int q = 0; q < 4; q++) acc[i][j][q] = 0.0f;

    const int KT = K >> 4;

    {
        cp_async16(&Ah[0][a_r][a_k], Ahg + (size_t)arow * K + a_k, a_ok);
        cp_async16(&Al[0][a_r][a_k], Alg + (size_t)arow * K + a_k, a_ok);
        if (is_bh)
            cp_async16(&Bh[0][b_r][b_c], Bhg + (size_t)b_r * N + colBase + b_c, true);
        else
            cp_async16(&Bl[0][b_r][b_c], Blg + (size_t)b_r * N + colBase + b_c, true);
        asm volatile("cp.async.commit_group;");
    }

    int buf = 0;
    for (int kt = 0; kt < KT; kt++) {
        asm volatile("cp.async.wait_group 0;");
        __syncthreads();

        if (kt + 1 < KT) {
            const int k0 = (kt + 1) << 4;
            const int nb = buf ^ 1;
            cp_async16(&Ah[nb][a_r][a_k], Ahg + (size_t)arow * K + k0 + a_k, a_ok);
            cp_async16(&Al[nb][a_r][a_k], Alg + (size_t)arow * K + k0 + a_k, a_ok);
            if (is_bh)
                cp_async16(&Bh[nb][b_r][b_c], Bhg + (size_t)(k0 + b_r) * N + colBase + b_c, true);
            else
                cp_async16(&Bl[nb][b_r][b_c], Blg + (size_t)(k0 + b_r) * N + colBase + b_c, true);
            asm volatile("cp.async.commit_group;");
        }

        uint32_t ah[2][4], al[2][4];
#pragma unroll
        for (int mf = 0; mf < 2; mf++) {
            const int m_base = warp_m * 32 + mf * 16;
            uint32_t addr_h = (uint32_t)__cvta_generic_to_shared(
                &Ah[buf][m_base + a_mloc][a_khalf * 8]);
            ldsm_x4(addr_h, ah[mf][0], ah[mf][1], ah[mf][2], ah[mf][3]);
            uint32_t addr_l = (uint32_t)__cvta_generic_to_shared(
                &Al[buf][m_base + a_mloc][a_khalf * 8]);
            ldsm_x4(addr_l, al[mf][0], al[mf][1], al[mf][2], al[mf][3]);
        }
        uint32_t bh[2][4], bl[2][4];
#pragma unroll
        for (int g = 0; g < 2; g++) {
            const int n_base = warp_n * 32 + g * 16;
            uint32_t addr_h = (uint32_t)__cvta_generic_to_shared(
                &Bh[buf][b_krow][n_base + b_nhalf * 8]);
            ldsm_x4_t(addr_h, bh[g][0], bh[g][1], bh[g][2], bh[g][3]);
            uint32_t addr_l = (uint32_t)__cvta_generic_to_shared(
                &Bl[buf][b_krow][n_base + b_nhalf * 8]);
            ldsm_x4_t(addr_l, bl[g][0], bl[g][1], bl[g][2], bl[g][3]);
        }
#pragma unroll
        for (int mf = 0; mf < 2; mf++) {
#pragma unroll
            for (int g = 0; g < 2; g++) {
#pragma unroll
                for (int h = 0; h < 2; h++) {
                    float* d = acc[mf][g * 2 + h];
                    const uint32_t bhp[2] = {bh[g][h * 2], bh[g][h * 2 + 1]};
                    const uint32_t blp[2] = {bl[g][h * 2], bl[g][h * 2 + 1]};
                    mma_bf16(d, ah[mf], bhp);
                    mma_bf16(d, ah[mf], blp);
                    mma_bf16(d, al[mf], bhp);
                }
            }
        }
        buf ^= 1;
    }

    const int lq = lane >> 2;
    const int lr = lane & 3;
#pragma unroll
    for (int mf = 0; mf < 2; mf++) {
#pragma unroll
        for (int g = 0; g < 2; g++) {
#pragma unroll
            for (int h = 0; h < 2; h++) {
                const float* d = acc[mf][g * 2 + h];
                const int col = colBase + warp_n * 32 + g * 16 + h * 8 + lr * 2;
                const int r0 = rowBase + warp_m * 32 + mf * 16 + lq;
                if (r0 < M)
                    *reinterpret_cast<float2*>(C + (size_t)r0 * N + col) =
                        make_float2(d[0], d[1]);
                const int r1 = r0 + 8;
                if (r1 < M)
                    *reinterpret_cast<float2*>(C + (size_t)r1 * N + col) =
                        make_float2(d[2], d[3]);
            }
        }
    }
}

// ---------------------------------------------------------------------------
// CSR aggregation. MODE 0: write fp32. MODE 1: relu + bf16 split write.
// ---------------------------------------------------------------------------
template <int MODE>
__global__ __launch_bounds__(256)
void agg_csr_kernel(const float* __restrict__ h, const float* __restrict__ bias,
                    const float* __restrict__ dinv,
                    const int* __restrict__ rowptr, const int* __restrict__ esrc,
                    const float* __restrict__ ecoef,
                    float* __restrict__ outf,
                    __nv_bfloat16* __restrict__ outh,
                    __nv_bfloat16* __restrict__ outl, int n) {
    const int node = blockIdx.x * 4 + (threadIdx.x >> 6);
    if (node >= n) return;
    const int c = (threadIdx.x & 63) << 2;

    const float di = dinv[node];
    const float wself = di * di;
    float4 hv = *reinterpret_cast<const float4*>(h + (size_t)node * DHID + c);
    float4 bb = *reinterpret_cast<const float4*>(bias + c);
    float4 acc;
    acc.x = fmaf(hv.x, wself, bb.x);
    acc.y = fmaf(hv.y, wself, bb.y);
    acc.z = fmaf(hv.z, wself, bb.z);
    acc.w = fmaf(hv.w, wself, bb.w);

    const int beg = rowptr[node];
    const int end = rowptr[node + 1];
    int e = beg;
    for (; e + 2 <= end; e += 2) {
        const int s0 = esrc[e];
        const int s1 = esrc[e + 1];
        const float c0 = ecoef[e];
        const float c1 = ecoef[e + 1];
        float4 v0 = *reinterpret_cast<const float4*>(h + (size_t)s0 * DHID + c);
        float4 v1 = *reinterpret_cast<const float4*>(h + (size_t)s1 * DHID + c);
        acc.x += c0 * v0.x + c1 * v1.x;
        acc.y += c0 * v0.y + c1 * v1.y;
        acc.z += c0 * v0.z + c1 * v1.z;
        acc.w += c0 * v0.w + c1 * v1.w;
    }
    if (e < end) {
        const int s0 = esrc[e];
        const float c0 = ecoef[e];
        float4 v0 = *reinterpret_cast<const float4*>(h + (size_t)s0 * DHID + c);
        acc.x += c0 * v0.x;
        acc.y += c0 * v0.y;
        acc.z += c0 * v0.z;
        acc.w += c0 * v0.w;
    }

    if (MODE == 0) {
        *reinterpret_cast<float4*>(outf + (size_t)node * DHID + c) = acc;
    } else {
        float v0 = fmaxf(acc.x, 0.f), v1 = fmaxf(acc.y, 0.f);
        float v2 = fmaxf(acc.z, 0.f), v3 = fmaxf(acc.w, 0.f);
        __nv_bfloat16 h0 = __float2bfloat16(v0);
        __nv_bfloat16 h1 = __float2bfloat16(v1);
        __nv_bfloat16 h2 = __float2bfloat16(v2);
        __nv_bfloat16 h3 = __float2bfloat16(v3);
        __nv_bfloat16 l0 = __float2bfloat16(v0 - __bfloat162float(h0));
        __nv_bfloat16 l1 = __float2bfloat16(v1 - __bfloat162float(h1));
        __nv_bfloat16 l2 = __float2bfloat16(v2 - __bfloat162float(h2));
        __nv_bfloat16 l3 = __float2bfloat16(v3 - __bfloat162float(h3));
        __nv_bfloat16* ph = outh + (size_t)node * DHID + c;
        __nv_bfloat16* pl = outl + (size_t)node * DHID + c;
        ph[0] = h0; ph[1] = h1; ph[2] = h2; ph[3] = h3;
        pl[0] = l0; pl[1] = l1; pl[2] = l2; pl[3] = l3;
    }
}

// ---------------------------------------------------------------------------
// Edge scoring (edge-parallel: one warp per edge) — R6 version
// ---------------------------------------------------------------------------
__global__ __launch_bounds__(256)
void score_kernel(const float* __restrict__ h,
                  const int* __restrict__ src,
                  const int* __restrict__ dst,
                  float* __restrict__ out, int e) {
    unsigned gt = blockIdx.x * blockDim.x + threadIdx.x;
    unsigned ed = gt >> 5;
    const int lane = threadIdx.x & 31;
    if (ed >= (unsigned)e) return;
    const int s = src[ed];
    const int d = dst[ed];
    const float4* ps = reinterpret_cast<const float4*>(h + (size_t)s * DHID) + lane * 2;
    const float4* pd = reinterpret_cast<const float4*>(h + (size_t)d * DHID) + lane * 2;
    float4 a0 = ps[0], a1 = ps[1];
    float4 b0 = pd[0], b1 = pd[1];
    float acc = a0.x * b0.x + a0.y * b0.y + a0.z * b0.z + a0.w * b0.w;
    acc += a1.x * b1.x + a1.y * b1.y + a1.z * b1.z + a1.w * b1.w;
#pragma unroll
    for (int off = 16; off > 0; off >>= 1)
        acc += __shfl_xor_sync(0xFFFFFFFFu, acc, off);
    if (lane == 0) out[ed] = 1.0f / (1.0f + expf(-acc));
}

// ---------------------------------------------------------------------------
// Host launcher — CSR build forked onto a side stream, overlapping split+GEMM1
// ---------------------------------------------------------------------------
extern "C" void kernel_launch(void* const* d_in, const int* in_sizes, int n_in,
                              void* d_out, int out_size) {
    const float* x  = (const float*)d_in[0];
    const int*   ei = (const int*)d_in[1];
    const float* W1 = (const float*)d_in[2];
    const float* b1 = (const float*)d_in[3];
    const float* W2 = (const float*)d_in[4];
    const float* b2 = (const float*)d_in[5];
    float* out = (float*)d_out;

    const int N = in_sizes[0] / DIN;
    const int E = in_sizes[1] / 2;
    const int* src = ei;
    const int* dst = ei + E;

    int *p_cnt, *p_rowptr, *p_off, *p_esrc, *p_bsum, *p_boff;
    float *p_dinv, *p_ecoef, *p_h1, *p_h2, *p_agg2;
    __nv_bfloat16 *p_xh, *p_xl, *p_w1h, *p_w1l, *p_w2h, *p_w2l, *p_a1h, *p_a1l;
    cudaGetSymbolAddress((void**)&p_cnt,    g_cnt);
    cudaGetSymbolAddress((void**)&p_dinv,   g_dinv);
    cudaGetSymbolAddress((void**)&p_rowptr, g_rowptr);
    cudaGetSymbolAddress((void**)&p_off,    g_off);
    cudaGetSymbolAddress((void**)&p_bsum,   g_blocksum);
    cudaGetSymbolAddress((void**)&p_boff,   g_blockoff);
    cudaGetSymbolAddress((void**)&p_esrc,   g_esrc);
    cudaGetSymbolAddress((void**)&p_ecoef,  g_ecoef);
    cudaGetSymbolAddress((void**)&p_xh,     g_xh);
    cudaGetSymbolAddress((void**)&p_xl,     g_xl);
    cudaGetSymbolAddress((void**)&p_w1h,    g_w1h);
    cudaGetSymbolAddress((void**)&p_w1l,    g_w1l);
    cudaGetSymbolAddress((void**)&p_w2h,    g_w2h);
    cudaGetSymbolAddress((void**)&p_w2l,    g_w2l);
    cudaGetSymbolAddress((void**)&p_h1,     g_h1);
    cudaGetSymbolAddress((void**)&p_a1h,    g_a1h);
    cudaGetSymbolAddress((void**)&p_a1l,    g_a1l);
    cudaGetSymbolAddress((void**)&p_h2,     g_h2);
    cudaGetSymbolAddress((void**)&p_agg2,   g_agg2);

    // Side stream + events, created once (first call is the uncaptured
    // correctness run; capture reuses them). Work is identical every call.
    static cudaStream_t s_side = nullptr;
    static cudaEvent_t  s_fork = nullptr, s_join = nullptr;
    if (s_side == nullptr) {
        cudaStreamCreateWithFlags(&s_side, cudaStreamNonBlocking);
        cudaEventCreateWithFlags(&s_fork, cudaEventDisableTiming);
        cudaEventCreateWithFlags(&s_join, cudaEventDisableTiming);
    }

    const int T = 256;

    // ---- fork: CSR build chain on side stream ----
    cudaEventRecord(s_fork, 0);
    cudaStreamWaitEvent(s_side, s_fork, 0);
    zero_cnt_kernel<<<(N + T - 1) / T, T, 0, s_side>>>(p_cnt, N);
    hist_kernel<<<(E + T - 1) / T, T, 0, s_side>>>(p_cnt, dst, E);
    dinv_kernel<<<(N + T - 1) / T, T, 0, s_side>>>(p_cnt, p_dinv, N);
    scan_p1_kernel<<<NB_SCAN, 256, 0, s_side>>>(p_cnt, p_bsum, N);
    scan_p2_kernel<<<1, NB_SCAN, 0, s_side>>>(p_bsum, p_boff, p_rowptr, N);
    scan_p3_kernel<<<NB_SCAN, 256, 0, s_side>>>(p_cnt, p_boff, p_rowptr, p_off, N);
    scatter_kernel<<<(E + T - 1) / T, T, 0, s_side>>>(src, dst, p_dinv, p_off,
                                                      p_esrc, p_ecoef, E);
    cudaEventRecord(s_join, s_side);

    // ---- main stream: splits + GEMM1 (independent of CSR) ----
    {
        int n4 = N * DIN / 4;
        split_kernel<<<(n4 + T - 1) / T, T>>>(x, p_xh, p_xl, n4);
        int w1n4 = DIN * DHID / 4;
        split_kernel<<<(w1n4 + T - 1) / T, T>>>(W1, p_w1h, p_w1l, w1n4);
        int w2n4 = DHID * DHID / 4;
        split_kernel<<<(w2n4 + T - 1) / T, T>>>(W2, p_w2h, p_w2l, w2n4);
    }
    {
        dim3 grid(DHID / 64, (N + 127) / 128);
        mma_gemm_pre_kernel<<<grid, 256>>>(p_xh, p_xl, p_w1h, p_w1l, p_h1, N, DIN, DHID);
    }

    // ---- join: agg1 needs CSR ----
    cudaStreamWaitEvent(0, s_join, 0);
    agg_csr_kernel<1><<<(N + 3) / 4, 256>>>(p_h1, b1, p_dinv, p_rowptr, p_esrc, p_ecoef,
                                            nullptr, p_a1h, p_a1l, N);

    {
        dim3 grid(DHID / 64, (N + 127) / 128);
        mma_gemm_pre_kernel<<<grid, 256>>>(p_a1h, p_a1l, p_w2h, p_w2l, p_h2, N, DHID, DHID);
    }
    agg_csr_kernel<0><<<(N + 3) / 4, 256>>>(p_h2, b2, p_dinv, p_rowptr, p_esrc, p_ecoef,
                                            p_agg2, nullptr, nullptr, N);

    // ---- edge scoring (edge-parallel) ----
    score_kernel<<<((unsigned)E * 32 + T - 1) / T, T>>>(p_agg2, src, dst, out, E);
}

// round 9
// speedup vs baseline: 1.1928x; 1.0399x over previous
#include <cuda_runtime.h>
#include <cuda_bf16.h>
#include <cuda_fp16.h>
#include <stdint.h>
#include <math.h>

#define MAX_N 50000
#define MAX_E 800000
#define DHID 256
#define DIN 512
#define NB_SCAN 128

// Scratch device globals
__device__ int   g_cnt[MAX_N];
__device__ float g_dinv[MAX_N];
__device__ int   g_rowptr[MAX_N + 1];
__device__ int   g_off[MAX_N];
__device__ int   g_blocksum[NB_SCAN];
__device__ int   g_blockoff[NB_SCAN];
__device__ int   g_esrc[MAX_E];
__device__ float g_ecoef[MAX_E];

__device__ __nv_bfloat16 g_xh[(size_t)MAX_N * DIN];
__device__ __nv_bfloat16 g_xl[(size_t)MAX_N * DIN];
__device__ __nv_bfloat16 g_w1h[DIN * DHID];
__device__ __nv_bfloat16 g_w1l[DIN * DHID];
__device__ __nv_bfloat16 g_w2h[DHID * DHID];
__device__ __nv_bfloat16 g_w2l[DHID * DHID];
__device__ float g_h1[(size_t)MAX_N * DHID];
__device__ __nv_bfloat16 g_a1h[(size_t)MAX_N * DHID];
__device__ __nv_bfloat16 g_a1l[(size_t)MAX_N * DHID];
__device__ float g_h2[(size_t)MAX_N * DHID];
__device__ __half g_agg2[(size_t)MAX_N * DHID];   // fp16: feeds score only

// ---------------------------------------------------------------------------
// CSR build
// ---------------------------------------------------------------------------
__global__ void zero_cnt_kernel(int* cnt, int n) {
    int i = blockIdx.x * blockDim.x + threadIdx.x;
    if (i < n) cnt[i] = 0;
}

__global__ void hist_kernel(int* cnt, const int* __restrict__ dst, int e) {
    int i = blockIdx.x * blockDim.x + threadIdx.x;
    if (i < e) atomicAdd(&cnt[dst[i]], 1);
}

__global__ void dinv_kernel(const int* __restrict__ cnt, float* __restrict__ dinv, int n) {
    int i = blockIdx.x * blockDim.x + threadIdx.x;
    if (i < n) dinv[i] = rsqrtf((float)(cnt[i] + 1));
}

__global__ __launch_bounds__(256)
void scan_p1_kernel(const int* __restrict__ cnt, int* __restrict__ blocksum, int n) {
    __shared__ int red[256];
    const int chunk = (n + NB_SCAN - 1) / NB_SCAN;
    const int beg = blockIdx.x * chunk;
    const int end = min(beg + chunk, n);
    int s = 0;
    for (int i = beg + threadIdx.x; i < end; i += 256) s += cnt[i];
    red[threadIdx.x] = s;
    __syncthreads();
    for (int d = 128; d > 0; d >>= 1) {
        if (threadIdx.x < d) red[threadIdx.x] += red[threadIdx.x + d];
        __syncthreads();
    }
    if (threadIdx.x == 0) blocksum[blockIdx.x] = red[0];
}

__global__ __launch_bounds__(NB_SCAN)
void scan_p2_kernel(const int* __restrict__ blocksum, int* __restrict__ blockoff,
                    int* __restrict__ rowptr, int n) {
    __shared__ int sh[NB_SCAN];
    const int t = threadIdx.x;
    sh[t] = blocksum[t];
    __syncthreads();
    for (int d = 1; d < NB_SCAN; d <<= 1) {
        int v = (t >= d) ? sh[t - d] : 0;
        __syncthreads();
        sh[t] += v;
        __syncthreads();
    }
    blockoff[t] = (t == 0) ? 0 : sh[t - 1];
    if (t == NB_SCAN - 1) rowptr[n] = sh[NB_SCAN - 1];
}

__global__ __launch_bounds__(256)
void scan_p3_kernel(const int* __restrict__ cnt, const int* __restrict__ blockoff,
                    int* __restrict__ rowptr, int* __restrict__ off, int n) {
    __shared__ int sh[256];
    const int chunk = (n + NB_SCAN - 1) / NB_SCAN;
    const int beg = blockIdx.x * chunk;
    const int end = min(beg + chunk, n);
    int running = blockoff[blockIdx.x];
    for (int base = beg; base < end; base += 256) {
        const int i = base + threadIdx.x;
        int v = (i < end) ? cnt[i] : 0;
        sh[threadIdx.x] = v;
        __syncthreads();
        for (int d = 1; d < 256; d <<= 1) {
            int t2 = (threadIdx.x >= d) ? sh[threadIdx.x - d] : 0;
            __syncthreads();
            sh[threadIdx.x] += t2;
            __syncthreads();
        }
        if (i < end) {
            const int excl = sh[threadIdx.x] - v;
            rowptr[i] = running + excl;
            off[i] = running + excl;
        }
        running += sh[255];
        __syncthreads();
    }
}

__global__ void scatter_kernel(const int* __restrict__ src, const int* __restrict__ dst,
                               const float* __restrict__ dinv, int* __restrict__ off,
                               int* __restrict__ esrc, float* __restrict__ ecoef, int e) {
    int i = blockIdx.x * blockDim.x + threadIdx.x;
    if (i < e) {
        const int s = src[i];
        const int d = dst[i];
        const int pos = atomicAdd(&off[d], 1);
        esrc[pos] = s;
        ecoef[pos] = dinv[s] * dinv[d];
    }
}

// ---------------------------------------------------------------------------
// fp32 -> (hi, lo) bf16 split
// ---------------------------------------------------------------------------
__global__ void split_kernel(const float* __restrict__ in,
                             __nv_bfloat16* __restrict__ hi,
                             __nv_bfloat16* __restrict__ lo, int n4) {
    int i = blockIdx.x * blockDim.x + threadIdx.x;
    if (i >= n4) return;
    float4 v = reinterpret_cast<const float4*>(in)[i];
    __nv_bfloat16 h0 = __float2bfloat16(v.x);
    __nv_bfloat16 h1 = __float2bfloat16(v.y);
    __nv_bfloat16 h2 = __float2bfloat16(v.z);
    __nv_bfloat16 h3 = __float2bfloat16(v.w);
    __nv_bfloat16 l0 = __float2bfloat16(v.x - __bfloat162float(h0));
    __nv_bfloat16 l1 = __float2bfloat16(v.y - __bfloat162float(h1));
    __nv_bfloat16 l2 = __float2bfloat16(v.z - __bfloat162float(h2));
    __nv_bfloat16 l3 = __float2bfloat16(v.w - __bfloat162float(h3));
    hi[i * 4 + 0] = h0; hi[i * 4 + 1] = h1; hi[i * 4 + 2] = h2; hi[i * 4 + 3] = h3;
    lo[i * 4 + 0] = l0; lo[i * 4 + 1] = l1; lo[i * 4 + 2] = l2; lo[i * 4 + 3] = l3;
}

// ---------------------------------------------------------------------------
// Tensor-core GEMM on pre-split bf16 operands (CTA 128x64, BK=16).
// ---------------------------------------------------------------------------
#define A_PAD 24
#define B_PAD 72

__device__ __forceinline__ void ldsm_x4(uint32_t addr, uint32_t& r0, uint32_t& r1,
                                        uint32_t& r2, uint32_t& r3) {
    asm volatile("ldmatrix.sync.aligned.m8n8.x4.shared.b16 {%0,%1,%2,%3}, [%4];"
                 : "=r"(r0), "=r"(r1), "=r"(r2), "=r"(r3) : "r"(addr));
}
__device__ __forceinline__ void ldsm_x4_t(uint32_t addr, uint32_t& r0, uint32_t& r1,
                                          uint32_t& r2, uint32_t& r3) {
    asm volatile("ldmatrix.sync.aligned.m8n8.x4.trans.shared.b16 {%0,%1,%2,%3}, [%4];"
                 : "=r"(r0), "=r"(r1), "=r"(r2), "=r"(r3) : "r"(addr));
}
__device__ __forceinline__ void mma_bf16(float* d, const uint32_t* a, const uint32_t* b) {
    asm volatile("mma.sync.aligned.m16n8k16.row.col.f32.bf16.bf16.f32 "
                 "{%0,%1,%2,%3}, {%4,%5,%6,%7}, {%8,%9}, {%0,%1,%2,%3};"
                 : "+f"(d[0]), "+f"(d[1]), "+f"(d[2]), "+f"(d[3])
                 : "r"(a[0]), "r"(a[1]), "r"(a[2]), "r"(a[3]), "r"(b[0]), "r"(b[1]));
}
__device__ __forceinline__ void cp_async16(void* smem_dst, const void* gsrc, bool pred) {
    uint32_t saddr = (uint32_t)__cvta_generic_to_shared(smem_dst);
    int sz = pred ? 16 : 0;
    asm volatile("cp.async.cg.shared.global [%0], [%1], 16, %2;"
                 :: "r"(saddr), "l"(gsrc), "r"(sz));
}

__global__ __launch_bounds__(256)
void mma_gemm_pre_kernel(const __nv_bfloat16* __restrict__ Ahg,
                         const __nv_bfloat16* __restrict__ Alg,
                         const __nv_bfloat16* __restrict__ Bhg,
                         const __nv_bfloat16* __restrict__ Blg,
                         float* __restrict__ C, int M, int K, int N) {
    __shared__ __nv_bfloat16 Ah[2][128][A_PAD];
    __shared__ __nv_bfloat16 Al[2][128][A_PAD];
    __shared__ __nv_bfloat16 Bh[2][16][B_PAD];
    __shared__ __nv_bfloat16 Bl[2][16][B_PAD];

    const int tid = threadIdx.x;
    const int wid = tid >> 5;
    const int lane = tid & 31;
    const int warp_m = wid & 3;
    const int warp_n = wid >> 2;
    const int rowBase = blockIdx.y * 128;
    const int colBase = blockIdx.x * 64;

    const int a_r = tid >> 1;
    const int a_k = (tid & 1) << 3;
    const int arow = rowBase + a_r;
    const bool a_ok = (arow < M);
    const int bt = tid & 127;
    const int b_r = bt >> 3;
    const int b_c = (bt & 7) << 3;
    const bool is_bh = (tid < 128);

    const int lrow = lane & 7;
    const int lmat = lane >> 3;
    const int a_mloc = ((lmat & 1) << 3) + lrow;
    const int a_khalf = lmat >> 1;
    const int b_krow = ((lmat & 1) << 3) + lrow;
    const int b_nhalf = lmat >> 1;

    float acc[2][4][4];
#pragma unroll
    for (int i = 0; i < 2; i++)
#pragma unroll
        for (int j = 0; j < 4; j++)
#pragma unroll
            for (int q = 0; q < 4; q++) acc[i][j][q] = 0.0f;

    const int KT = K >> 4;

    {
        cp_async16(&Ah[0][a_r][a_k], Ahg + (size_t)arow * K + a_k, a_ok);
        cp_async16(&Al[0][a_r][a_k], Alg + (size_t)arow * K + a_k, a_ok);
        if (is_bh)
            cp_async16(&Bh[0][b_r][b_c], Bhg + (size_t)b_r * N + colBase + b_c, true);
        else
            cp_async16(&Bl[0][b_r][b_c], Blg + (size_t)b_r * N + colBase + b_c, true);
        asm volatile("cp.async.commit_group;");
    }

    int buf = 0;
    for (int kt = 0; kt < KT; kt++) {
        asm volatile("cp.async.wait_group 0;");
        __syncthreads();

        if (kt + 1 < KT) {
            const int k0 = (kt + 1) << 4;
            const int nb = buf ^ 1;
            cp_async16(&Ah[nb][a_r][a_k], Ahg + (size_t)arow * K + k0 + a_k, a_ok);
            cp_async16(&Al[nb][a_r][a_k], Alg + (size_t)arow * K + k0 + a_k, a_ok);
            if (is_bh)
                cp_async16(&Bh[nb][b_r][b_c], Bhg + (size_t)(k0 + b_r) * N + colBase + b_c, true);
            else
                cp_async16(&Bl[nb][b_r][b_c], Blg + (size_t)(k0 + b_r) * N + colBase + b_c, true);
            asm volatile("cp.async.commit_group;");
        }

        uint32_t ah[2][4], al[2][4];
#pragma unroll
        for (int mf = 0; mf < 2; mf++) {
            const int m_base = warp_m * 32 + mf * 16;
            uint32_t addr_h = (uint32_t)__cvta_generic_to_shared(
                &Ah[buf][m_base + a_mloc][a_khalf * 8]);
            ldsm_x4(addr_h, ah[mf][0], ah[mf][1], ah[mf][2], ah[mf][3]);
            uint32_t addr_l = (uint32_t)__cvta_generic_to_shared(
                &Al[buf][m_base + a_mloc][a_khalf * 8]);
            ldsm_x4(addr_l, al[mf][0], al[mf][1], al[mf][2], al[mf][3]);
        }
        uint32_t bh[2][4], bl[2][4];
#pragma unroll
        for (int g = 0; g < 2; g++) {
            const int n_base = warp_n * 32 + g * 16;
            uint32_t addr_h = (uint32_t)__cvta_generic_to_shared(
                &Bh[buf][b_krow][n_base + b_nhalf * 8]);
            ldsm_x4_t(addr_h, bh[g][0], bh[g][1], bh[g][2], bh[g][3]);
            uint32_t addr_l = (uint32_t)__cvta_generic_to_shared(
                &Bl[buf][b_krow][n_base + b_nhalf * 8]);
            ldsm_x4_t(addr_l, bl[g][0], bl[g][1], bl[g][2], bl[g][3]);
        }
#pragma unroll
        for (int mf = 0; mf < 2; mf++) {
#pragma unroll
            for (int g = 0; g < 2; g++) {
#pragma unroll
                for (int h = 0; h < 2; h++) {
                    float* d = acc[mf][g * 2 + h];
                    const uint32_t bhp[2] = {bh[g][h * 2], bh[g][h * 2 + 1]};
                    const uint32_t blp[2] = {bl[g][h * 2], bl[g][h * 2 + 1]};
                    mma_bf16(d, ah[mf], bhp);
                    mma_bf16(d, ah[mf], blp);
                    mma_bf16(d, al[mf], bhp);
                }
            }
        }
        buf ^= 1;
    }

    const int lq = lane >> 2;
    const int lr = lane & 3;
#pragma unroll
    for (int mf = 0; mf < 2; mf++) {
#pragma unroll
        for (int g = 0; g < 2; g++) {
#pragma unroll
            for (int h = 0; h < 2; h++) {
                const float* d = acc[mf][g * 2 + h];
                const int col = colBase + warp_n * 32 + g * 16 + h * 8 + lr * 2;
                const int r0 = rowBase + warp_m * 32 + mf * 16 + lq;
                if (r0 < M)
                    *reinterpret_cast<float2*>(C + (size_t)r0 * N + col) =
                        make_float2(d[0], d[1]);
                const int r1 = r0 + 8;
                if (r1 < M)
                    *reinterpret_cast<float2*>(C + (size_t)r1 * N + col) =
                        make_float2(d[2], d[3]);
            }
        }
    }
}

// ---------------------------------------------------------------------------
// CSR aggregation. MODE 1: relu + bf16 split write (feeds GEMM2).
//                   MODE 2: fp16 write (feeds score only).
// ---------------------------------------------------------------------------
template <int MODE>
__global__ __launch_bounds__(256)
void agg_csr_kernel(const float* __restrict__ h, const float* __restrict__ bias,
                    const float* __restrict__ dinv,
                    const int* __restrict__ rowptr, const int* __restrict__ esrc,
                    const float* __restrict__ ecoef,
                    __half* __restrict__ outfp16,
                    __nv_bfloat16* __restrict__ outh,
                    __nv_bfloat16* __restrict__ outl, int n) {
    const int node = blockIdx.x * 4 + (threadIdx.x >> 6);
    if (node >= n) return;
    const int c = (threadIdx.x & 63) << 2;

    const float di = dinv[node];
    const float wself = di * di;
    float4 hv = *reinterpret_cast<const float4*>(h + (size_t)node * DHID + c);
    float4 bb = *reinterpret_cast<const float4*>(bias + c);
    float4 acc;
    acc.x = fmaf(hv.x, wself, bb.x);
    acc.y = fmaf(hv.y, wself, bb.y);
    acc.z = fmaf(hv.z, wself, bb.z);
    acc.w = fmaf(hv.w, wself, bb.w);

    const int beg = rowptr[node];
    const int end = rowptr[node + 1];
    int e = beg;
    for (; e + 2 <= end; e += 2) {
        const int s0 = esrc[e];
        const int s1 = esrc[e + 1];
        const float c0 = ecoef[e];
        const float c1 = ecoef[e + 1];
        float4 v0 = *reinterpret_cast<const float4*>(h + (size_t)s0 * DHID + c);
        float4 v1 = *reinterpret_cast<const float4*>(h + (size_t)s1 * DHID + c);
        acc.x += c0 * v0.x + c1 * v1.x;
        acc.y += c0 * v0.y + c1 * v1.y;
        acc.z += c0 * v0.z + c1 * v1.z;
        acc.w += c0 * v0.w + c1 * v1.w;
    }
    if (e < end) {
        const int s0 = esrc[e];
        const float c0 = ecoef[e];
        float4 v0 = *reinterpret_cast<const float4*>(h + (size_t)s0 * DHID + c);
        acc.x += c0 * v0.x;
        acc.y += c0 * v0.y;
        acc.z += c0 * v0.z;
        acc.w += c0 * v0.w;
    }

    if (MODE == 2) {
        __half2 p0 = __floats2half2_rn(acc.x, acc.y);
        __half2 p1 = __floats2half2_rn(acc.z, acc.w);
        *reinterpret_cast<__half2*>(outfp16 + (size_t)node * DHID + c) = p0;
        *reinterpret_cast<__half2*>(outfp16 + (size_t)node * DHID + c + 2) = p1;
    } else {
        float v0 = fmaxf(acc.x, 0.f), v1 = fmaxf(acc.y, 0.f);
        float v2 = fmaxf(acc.z, 0.f), v3 = fmaxf(acc.w, 0.f);
        __nv_bfloat16 h0 = __float2bfloat16(v0);
        __nv_bfloat16 h1 = __float2bfloat16(v1);
        __nv_bfloat16 h2 = __float2bfloat16(v2);
        __nv_bfloat16 h3 = __float2bfloat16(v3);
        __nv_bfloat16 l0 = __float2bfloat16(v0 - __bfloat162float(h0));
        __nv_bfloat16 l1 = __float2bfloat16(v1 - __bfloat162float(h1));
        __nv_bfloat16 l2 = __float2bfloat16(v2 - __bfloat162float(h2));
        __nv_bfloat16 l3 = __float2bfloat16(v3 - __bfloat162float(h3));
        __nv_bfloat16* ph = outh + (size_t)node * DHID + c;
        __nv_bfloat16* pl = outl + (size_t)node * DHID + c;
        ph[0] = h0; ph[1] = h1; ph[2] = h2; ph[3] = h3;
        pl[0] = l0; pl[1] = l1; pl[2] = l2; pl[3] = l3;
    }
}

// ---------------------------------------------------------------------------
// Edge scoring from fp16 features (one warp per edge, fp32 accumulate).
// Row = 256 fp16 = 512B; lane loads one uint4 (8 halfs) from each endpoint.
// ---------------------------------------------------------------------------
__global__ __launch_bounds__(256)
void score_fp16_kernel(const __half* __restrict__ h,
                       const int* __restrict__ src,
                       const int* __restrict__ dst,
                       float* __restrict__ out, int e) {
    unsigned gt = blockIdx.x * blockDim.x + threadIdx.x;
    unsigned ed = gt >> 5;
    const int lane = threadIdx.x & 31;
    if (ed >= (unsigned)e) return;
    const int s = src[ed];
    const int d = dst[ed];
    const __half2* ps = reinterpret_cast<const __half2*>(h + (size_t)s * DHID) + lane * 4;
    const __half2* pd = reinterpret_cast<const __half2*>(h + (size_t)d * DHID) + lane * 4;
    // 16B vector loads
    uint4 su = *reinterpret_cast<const uint4*>(ps);
    uint4 du = *reinterpret_cast<const uint4*>(pd);
    const __half2* sv = reinterpret_cast<const __half2*>(&su);
    const __half2* dv = reinterpret_cast<const __half2*>(&du);
    float acc = 0.0f;
#pragma unroll
    for (int i = 0; i < 4; i++) {
        float2 a = __half22float2(sv[i]);
        float2 b = __half22float2(dv[i]);
        acc = fmaf(a.x, b.x, acc);
        acc = fmaf(a.y, b.y, acc);
    }
#pragma unroll
    for (int off = 16; off > 0; off >>= 1)
        acc += __shfl_xor_sync(0xFFFFFFFFu, acc, off);
    if (lane == 0) out[ed] = 1.0f / (1.0f + expf(-acc));
}

// ---------------------------------------------------------------------------
// Host launcher — CSR build forked onto a side stream
// ---------------------------------------------------------------------------
extern "C" void kernel_launch(void* const* d_in, const int* in_sizes, int n_in,
                              void* d_out, int out_size) {
    const float* x  = (const float*)d_in[0];
    const int*   ei = (const int*)d_in[1];
    const float* W1 = (const float*)d_in[2];
    const float* b1 = (const float*)d_in[3];
    const float* W2 = (const float*)d_in[4];
    const float* b2 = (const float*)d_in[5];
    float* out = (float*)d_out;

    const int N = in_sizes[0] / DIN;
    const int E = in_sizes[1] / 2;
    const int* src = ei;
    const int* dst = ei + E;

    int *p_cnt, *p_rowptr, *p_off, *p_esrc, *p_bsum, *p_boff;
    float *p_dinv, *p_ecoef, *p_h1, *p_h2;
    __half *p_agg2;
    __nv_bfloat16 *p_xh, *p_xl, *p_w1h, *p_w1l, *p_w2h, *p_w2l, *p_a1h, *p_a1l;
    cudaGetSymbolAddress((void**)&p_cnt,    g_cnt);
    cudaGetSymbolAddress((void**)&p_dinv,   g_dinv);
    cudaGetSymbolAddress((void**)&p_rowptr, g_rowptr);
    cudaGetSymbolAddress((void**)&p_off,    g_off);
    cudaGetSymbolAddress((void**)&p_bsum,   g_blocksum);
    cudaGetSymbolAddress((void**)&p_boff,   g_blockoff);
    cudaGetSymbolAddress((void**)&p_esrc,   g_esrc);
    cudaGetSymbolAddress((void**)&p_ecoef,  g_ecoef);
    cudaGetSymbolAddress((void**)&p_xh,     g_xh);
    cudaGetSymbolAddress((void**)&p_xl,     g_xl);
    cudaGetSymbolAddress((void**)&p_w1h,    g_w1h);
    cudaGetSymbolAddress((void**)&p_w1l,    g_w1l);
    cudaGetSymbolAddress((void**)&p_w2h,    g_w2h);
    cudaGetSymbolAddress((void**)&p_w2l,    g_w2l);
    cudaGetSymbolAddress((void**)&p_h1,     g_h1);
    cudaGetSymbolAddress((void**)&p_a1h,    g_a1h);
    cudaGetSymbolAddress((void**)&p_a1l,    g_a1l);
    cudaGetSymbolAddress((void**)&p_h2,     g_h2);
    cudaGetSymbolAddress((void**)&p_agg2,   g_agg2);

    static cudaStream_t s_side = nullptr;
    static cudaEvent_t  s_fork = nullptr, s_join = nullptr;
    if (s_side == nullptr) {
        cudaStreamCreateWithFlags(&s_side, cudaStreamNonBlocking);
        cudaEventCreateWithFlags(&s_fork, cudaEventDisableTiming);
        cudaEventCreateWithFlags(&s_join, cudaEventDisableTiming);
    }

    const int T = 256;

    // ---- fork: CSR build chain on side stream ----
    cudaEventRecord(s_fork, 0);
    cudaStreamWaitEvent(s_side, s_fork, 0);
    zero_cnt_kernel<<<(N + T - 1) / T, T, 0, s_side>>>(p_cnt, N);
    hist_kernel<<<(E + T - 1) / T, T, 0, s_side>>>(p_cnt, dst, E);
    dinv_kernel<<<(N + T - 1) / T, T, 0, s_side>>>(p_cnt, p_dinv, N);
    scan_p1_kernel<<<NB_SCAN, 256, 0, s_side>>>(p_cnt, p_bsum, N);
    scan_p2_kernel<<<1, NB_SCAN, 0, s_side>>>(p_bsum, p_boff, p_rowptr, N);
    scan_p3_kernel<<<NB_SCAN, 256, 0, s_side>>>(p_cnt, p_boff, p_rowptr, p_off, N);
    scatter_kernel<<<(E + T - 1) / T, T, 0, s_side>>>(src, dst, p_dinv, p_off,
                                                      p_esrc, p_ecoef, E);
    cudaEventRecord(s_join, s_side);

    // ---- main stream: splits + GEMM1 ----
    {
        int n4 = N * DIN / 4;
        split_kernel<<<(n4 + T - 1) / T, T>>>(x, p_xh, p_xl, n4);
        int w1n4 = DIN * DHID / 4;
        split_kernel<<<(w1n4 + T - 1) / T, T>>>(W1, p_w1h, p_w1l, w1n4);
        int w2n4 = DHID * DHID / 4;
        split_kernel<<<(w2n4 + T - 1) / T, T>>>(W2, p_w2h, p_w2l, w2n4);
    }
    {
        dim3 grid(DHID / 64, (N + 127) / 128);
        mma_gemm_pre_kernel<<<grid, 256>>>(p_xh, p_xl, p_w1h, p_w1l, p_h1, N, DIN, DHID);
    }

    // ---- join: agg1 needs CSR ----
    cudaStreamWaitEvent(0, s_join, 0);
    agg_csr_kernel<1><<<(N + 3) / 4, 256>>>(p_h1, b1, p_dinv, p_rowptr, p_esrc, p_ecoef,
                                            nullptr, p_a1h, p_a1l, N);

    {
        dim3 grid(DHID / 64, (N + 127) / 128);
        mma_gemm_pre_kernel<<<grid, 256>>>(p_a1h, p_a1l, p_w2h, p_w2l, p_h2, N, DHID, DHID);
    }
    agg_csr_kernel<2><<<(N + 3) / 4, 256>>>(p_h2, b2, p_dinv, p_rowptr, p_esrc, p_ecoef,
                                            p_agg2, nullptr, nullptr, N);

    // ---- edge scoring from fp16 (half the L2 traffic) ----
    score_fp16_kernel<<<((unsigned)E * 32 + T - 1) / T, T>>>(p_agg2, src, dst, out, E);
}

// round 10
// speedup vs baseline: 1.2246x; 1.0266x over previous
#include <cuda_runtime.h>
#include <cuda_bf16.h>
#include <cuda_fp16.h>
#include <stdint.h>
#include <math.h>

#define MAX_N 50000
#define MAX_E 800000
#define DHID 256
#define DIN 512
#define NB_SCAN 128

// Scratch device globals
__device__ int   g_cnt[MAX_N];
__device__ float g_dinv[MAX_N];
__device__ int   g_rowptr[MAX_N + 1];
__device__ int   g_off[MAX_N];
__device__ int   g_blocksum[NB_SCAN];
__device__ int   g_blockoff[NB_SCAN];
__device__ int   g_esrc[MAX_E];
__device__ float g_ecoef[MAX_E];

__device__ __nv_bfloat16 g_xh[(size_t)MAX_N * DIN];
__device__ __nv_bfloat16 g_xl[(size_t)MAX_N * DIN];
__device__ __nv_bfloat16 g_w1h[DIN * DHID];
__device__ __nv_bfloat16 g_w1l[DIN * DHID];
__device__ __nv_bfloat16 g_w2h[DHID * DHID];
__device__ __nv_bfloat16 g_w2l[DHID * DHID];
__device__ __half g_h1[(size_t)MAX_N * DHID];     // fp16 GEMM1 output
__device__ __nv_bfloat16 g_a1h[(size_t)MAX_N * DHID];
__device__ __nv_bfloat16 g_a1l[(size_t)MAX_N * DHID];
__device__ __half g_h2[(size_t)MAX_N * DHID];     // fp16 GEMM2 output
__device__ __half g_agg2[(size_t)MAX_N * DHID];   // fp16: feeds score only

// ---------------------------------------------------------------------------
// CSR build
// ---------------------------------------------------------------------------
__global__ void zero_cnt_kernel(int* cnt, int n) {
    int i = blockIdx.x * blockDim.x + threadIdx.x;
    if (i < n) cnt[i] = 0;
}

__global__ void hist_kernel(int* cnt, const int* __restrict__ dst, int e) {
    int i = blockIdx.x * blockDim.x + threadIdx.x;
    if (i < e) atomicAdd(&cnt[dst[i]], 1);
}

__global__ void dinv_kernel(const int* __restrict__ cnt, float* __restrict__ dinv, int n) {
    int i = blockIdx.x * blockDim.x + threadIdx.x;
    if (i < n) dinv[i] = rsqrtf((float)(cnt[i] + 1));
}

__global__ __launch_bounds__(256)
void scan_p1_kernel(const int* __restrict__ cnt, int* __restrict__ blocksum, int n) {
    __shared__ int red[256];
    const int chunk = (n + NB_SCAN - 1) / NB_SCAN;
    const int beg = blockIdx.x * chunk;
    const int end = min(beg + chunk, n);
    int s = 0;
    for (int i = beg + threadIdx.x; i < end; i += 256) s += cnt[i];
    red[threadIdx.x] = s;
    __syncthreads();
    for (int d = 128; d > 0; d >>= 1) {
        if (threadIdx.x < d) red[threadIdx.x] += red[threadIdx.x + d];
        __syncthreads();
    }
    if (threadIdx.x == 0) blocksum[blockIdx.x] = red[0];
}

__global__ __launch_bounds__(NB_SCAN)
void scan_p2_kernel(const int* __restrict__ blocksum, int* __restrict__ blockoff,
                    int* __restrict__ rowptr, int n) {
    __shared__ int sh[NB_SCAN];
    const int t = threadIdx.x;
    sh[t] = blocksum[t];
    __syncthreads();
    for (int d = 1; d < NB_SCAN; d <<= 1) {
        int v = (t >= d) ? sh[t - d] : 0;
        __syncthreads();
        sh[t] += v;
        __syncthreads();
    }
    blockoff[t] = (t == 0) ? 0 : sh[t - 1];
    if (t == NB_SCAN - 1) rowptr[n] = sh[NB_SCAN - 1];
}

__global__ __launch_bounds__(256)
void scan_p3_kernel(const int* __restrict__ cnt, const int* __restrict__ blockoff,
                    int* __restrict__ rowptr, int* __restrict__ off, int n) {
    __shared__ int sh[256];
    const int chunk = (n + NB_SCAN - 1) / NB_SCAN;
    const int beg = blockIdx.x * chunk;
    const int end = min(beg + chunk, n);
    int running = blockoff[blockIdx.x];
    for (int base = beg; base < end; base += 256) {
        const int i = base + threadIdx.x;
        int v = (i < end) ? cnt[i] : 0;
        sh[threadIdx.x] = v;
        __syncthreads();
        for (int d = 1; d < 256; d <<= 1) {
            int t2 = (threadIdx.x >= d) ? sh[threadIdx.x - d] : 0;
            __syncthreads();
            sh[threadIdx.x] += t2;
            __syncthreads();
        }
        if (i < end) {
            const int excl = sh[threadIdx.x] - v;
            rowptr[i] = running + excl;
            off[i] = running + excl;
        }
        running += sh[255];
        __syncthreads();
    }
}

__global__ void scatter_kernel(const int* __restrict__ src, const int* __restrict__ dst,
                               const float* __restrict__ dinv, int* __restrict__ off,
                               int* __restrict__ esrc, float* __restrict__ ecoef, int e) {
    int i = blockIdx.x * blockDim.x + threadIdx.x;
    if (i < e) {
        const int s = src[i];
        const int d = dst[i];
        const int pos = atomicAdd(&off[d], 1);
        esrc[pos] = s;
        ecoef[pos] = dinv[s] * dinv[d];
    }
}

// ---------------------------------------------------------------------------
// fp32 -> (hi, lo) bf16 split
// ---------------------------------------------------------------------------
__global__ void split_kernel(const float* __restrict__ in,
                             __nv_bfloat16* __restrict__ hi,
                             __nv_bfloat16* __restrict__ lo, int n4) {
    int i = blockIdx.x * blockDim.x + threadIdx.x;
    if (i >= n4) return;
    float4 v = reinterpret_cast<const float4*>(in)[i];
    __nv_bfloat16 h0 = __float2bfloat16(v.x);
    __nv_bfloat16 h1 = __float2bfloat16(v.y);
    __nv_bfloat16 h2 = __float2bfloat16(v.z);
    __nv_bfloat16 h3 = __float2bfloat16(v.w);
    __nv_bfloat16 l0 = __float2bfloat16(v.x - __bfloat162float(h0));
    __nv_bfloat16 l1 = __float2bfloat16(v.y - __bfloat162float(h1));
    __nv_bfloat16 l2 = __float2bfloat16(v.z - __bfloat162float(h2));
    __nv_bfloat16 l3 = __float2bfloat16(v.w - __bfloat162float(h3));
    hi[i * 4 + 0] = h0; hi[i * 4 + 1] = h1; hi[i * 4 + 2] = h2; hi[i * 4 + 3] = h3;
    lo[i * 4 + 0] = l0; lo[i * 4 + 1] = l1; lo[i * 4 + 2] = l2; lo[i * 4 + 3] = l3;
}

// ---------------------------------------------------------------------------
// Tensor-core GEMM on pre-split bf16 operands (CTA 128x64, BK=16).
// Epilogue writes fp16 (C feeds only gather/aggregate stages).
// ---------------------------------------------------------------------------
#define A_PAD 24
#define B_PAD 72

__device__ __forceinline__ void ldsm_x4(uint32_t addr, uint32_t& r0, uint32_t& r1,
                                        uint32_t& r2, uint32_t& r3) {
    asm volatile("ldmatrix.sync.aligned.m8n8.x4.shared.b16 {%0,%1,%2,%3}, [%4];"
                 : "=r"(r0), "=r"(r1), "=r"(r2), "=r"(r3) : "r"(addr));
}
__device__ __forceinline__ void ldsm_x4_t(uint32_t addr, uint32_t& r0, uint32_t& r1,
                                          uint32_t& r2, uint32_t& r3) {
    asm volatile("ldmatrix.sync.aligned.m8n8.x4.trans.shared.b16 {%0,%1,%2,%3}, [%4];"
                 : "=r"(r0), "=r"(r1), "=r"(r2), "=r"(r3) : "r"(addr));
}
__device__ __forceinline__ void mma_bf16(float* d, const uint32_t* a, const uint32_t* b) {
    asm volatile("mma.sync.aligned.m16n8k16.row.col.f32.bf16.bf16.f32 "
                 "{%0,%1,%2,%3}, {%4,%5,%6,%7}, {%8,%9}, {%0,%1,%2,%3};"
                 : "+f"(d[0]), "+f"(d[1]), "+f"(d[2]), "+f"(d[3])
                 : "r"(a[0]), "r"(a[1]), "r"(a[2]), "r"(a[3]), "r"(b[0]), "r"(b[1]));
}
__device__ __forceinline__ void cp_async16(void* smem_dst, const void* gsrc, bool pred) {
    uint32_t saddr = (uint32_t)__cvta_generic_to_shared(smem_dst);
    int sz = pred ? 16 : 0;
    asm volatile("cp.async.cg.shared.global [%0], [%1], 16, %2;"
                 :: "r"(saddr), "l"(gsrc), "r"(sz));
}

__global__ __launch_bounds__(256)
void mma_gemm_pre_kernel(const __nv_bfloat16* __restrict__ Ahg,
                         const __nv_bfloat16* __restrict__ Alg,
                         const __nv_bfloat16* __restrict__ Bhg,
                         const __nv_bfloat16* __restrict__ Blg,
                         __half* __restrict__ C, int M, int K, int N) {
    __shared__ __nv_bfloat16 Ah[2][128][A_PAD];
    __shared__ __nv_bfloat16 Al[2][128][A_PAD];
    __shared__ __nv_bfloat16 Bh[2][16][B_PAD];
    __shared__ __nv_bfloat16 Bl[2][16][B_PAD];

    const int tid = threadIdx.x;
    const int wid = tid >> 5;
    const int lane = tid & 31;
    const int warp_m = wid & 3;
    const int warp_n = wid >> 2;
    const int rowBase = blockIdx.y * 128;
    const int colBase = blockIdx.x * 64;

    const int a_r = tid >> 1;
    const int a_k = (tid & 1) << 3;
    const int arow = rowBase + a_r;
    const bool a_ok = (arow < M);
    const int bt = tid & 127;
    const int b_r = bt >> 3;
    const int b_c = (bt & 7) << 3;
    const bool is_bh = (tid < 128);

    const int lrow = lane & 7;
    const int lmat = lane >> 3;
    const int a_mloc = ((lmat & 1) << 3) + lrow;
    const int a_khalf = lmat >> 1;
    const int b_krow = ((lmat & 1) << 3) + lrow;
    const int b_nhalf = lmat >> 1;

    float acc[2][4][4];
#pragma unroll
    for (int i = 0; i < 2; i++)
#pragma unroll
        for (int j = 0; j < 4; j++)
#pragma unroll
            for (int q = 0; q < 4; q++) acc[i][j][q] = 0.0f;

    const int KT = K >> 4;

    {
        cp_async16(&Ah[0][a_r][a_k], Ahg + (size_t)arow * K + a_k, a_ok);
        cp_async16(&Al[0][a_r][a_k], Alg + (size_t)arow * K + a_k, a_ok);
        if (is_bh)
            cp_async16(&Bh[0][b_r][b_c], Bhg + (size_t)b_r * N + colBase + b_c, true);
        else
            cp_async16(&Bl[0][b_r][b_c], Blg + (size_t)b_r * N + colBase + b_c, true);
        asm volatile("cp.async.commit_group;");
    }

    int buf = 0;
    for (int kt = 0; kt < KT; kt++) {
        asm volatile("cp.async.wait_group 0;");
        __syncthreads();

        if (kt + 1 < KT) {
            const int k0 = (kt + 1) << 4;
            const int nb = buf ^ 1;
            cp_async16(&Ah[nb][a_r][a_k], Ahg + (size_t)arow * K + k0 + a_k, a_ok);
            cp_async16(&Al[nb][a_r][a_k], Alg + (size_t)arow * K + k0 + a_k, a_ok);
            if (is_bh)
                cp_async16(&Bh[nb][b_r][b_c], Bhg + (size_t)(k0 + b_r) * N + colBase + b_c, true);
            else
                cp_async16(&Bl[nb][b_r][b_c], Blg + (size_t)(k0 + b_r) * N + colBase + b_c, true);
            asm volatile("cp.async.commit_group;");
        }

        uint32_t ah[2][4], al[2][4];
#pragma unroll
        for (int mf = 0; mf < 2; mf++) {
            const int m_base = warp_m * 32 + mf * 16;
            uint32_t addr_h = (uint32_t)__cvta_generic_to_shared(
                &Ah[buf][m_base + a_mloc][a_khalf * 8]);
            ldsm_x4(addr_h, ah[mf][0], ah[mf][1], ah[mf][2], ah[mf][3]);
            uint32_t addr_l = (uint32_t)__cvta_generic_to_shared(
                &Al[buf][m_base + a_mloc][a_khalf * 8]);
            ldsm_x4(addr_l, al[mf][0], al[mf][1], al[mf][2], al[mf][3]);
        }
        uint32_t bh[2][4], bl[2][4];
#pragma unroll
        for (int g = 0; g < 2; g++) {
            const int n_base = warp_n * 32 + g * 16;
            uint32_t addr_h = (uint32_t)__cvta_generic_to_shared(
                &Bh[buf][b_krow][n_base + b_nhalf * 8]);
            ldsm_x4_t(addr_h, bh[g][0], bh[g][1], bh[g][2], bh[g][3]);
            uint32_t addr_l = (uint32_t)__cvta_generic_to_shared(
                &Bl[buf][b_krow][n_base + b_nhalf * 8]);
            ldsm_x4_t(addr_l, bl[g][0], bl[g][1], bl[g][2], bl[g][3]);
        }
#pragma unroll
        for (int mf = 0; mf < 2; mf++) {
#pragma unroll
            for (int g = 0; g < 2; g++) {
#pragma unroll
                for (int h = 0; h < 2; h++) {
                    float* d = acc[mf][g * 2 + h];
                    const uint32_t bhp[2] = {bh[g][h * 2], bh[g][h * 2 + 1]};
                    const uint32_t blp[2] = {bl[g][h * 2], bl[g][h * 2 + 1]};
                    mma_bf16(d, ah[mf], bhp);
                    mma_bf16(d, ah[mf], blp);
                    mma_bf16(d, al[mf], bhp);
                }
            }
        }
        buf ^= 1;
    }

    const int lq = lane >> 2;
    const int lr = lane & 3;
#pragma unroll
    for (int mf = 0; mf < 2; mf++) {
#pragma unroll
        for (int g = 0; g < 2; g++) {
#pragma unroll
            for (int h = 0; h < 2; h++) {
                const float* d = acc[mf][g * 2 + h];
                const int col = colBase + warp_n * 32 + g * 16 + h * 8 + lr * 2;
                const int r0 = rowBase + warp_m * 32 + mf * 16 + lq;
                if (r0 < M)
                    *reinterpret_cast<__half2*>(C + (size_t)r0 * N + col) =
                        __floats2half2_rn(d[0], d[1]);
                const int r1 = r0 + 8;
                if (r1 < M)
                    *reinterpret_cast<__half2*>(C + (size_t)r1 * N + col) =
                        __floats2half2_rn(d[2], d[3]);
            }
        }
    }
}

// ---------------------------------------------------------------------------
// CSR aggregation from fp16 h. fp32 accumulate.
// MODE 1: relu + bf16 split write (feeds GEMM2). MODE 2: fp16 write (score).
// Each thread: 4 dims = 8B loads (half4 via uint2-sized __half2 pairs).
// ---------------------------------------------------------------------------
template <int MODE>
__global__ __launch_bounds__(256)
void agg_csr_kernel(const __half* __restrict__ h, const float* __restrict__ bias,
                    const float* __restrict__ dinv,
                    const int* __restrict__ rowptr, const int* __restrict__ esrc,
                    const float* __restrict__ ecoef,
                    __half* __restrict__ outfp16,
                    __nv_bfloat16* __restrict__ outh,
                    __nv_bfloat16* __restrict__ outl, int n) {
    const int node = blockIdx.x * 4 + (threadIdx.x >> 6);
    if (node >= n) return;
    const int c = (threadIdx.x & 63) << 2;

    const float di = dinv[node];
    const float wself = di * di;
    const __half2* hp = reinterpret_cast<const __half2*>(h + (size_t)node * DHID + c);
    float2 h01 = __half22float2(hp[0]);
    float2 h23 = __half22float2(hp[1]);
    float4 bb = *reinterpret_cast<const float4*>(bias + c);
    float4 acc;
    acc.x = fmaf(h01.x, wself, bb.x);
    acc.y = fmaf(h01.y, wself, bb.y);
    acc.z = fmaf(h23.x, wself, bb.z);
    acc.w = fmaf(h23.y, wself, bb.w);

    const int beg = rowptr[node];
    const int end = rowptr[node + 1];
    int e = beg;
    for (; e + 2 <= end; e += 2) {
        const int s0 = esrc[e];
        const int s1 = esrc[e + 1];
        const float c0 = ecoef[e];
        const float c1 = ecoef[e + 1];
        const __half2* p0 = reinterpret_cast<const __half2*>(h + (size_t)s0 * DHID + c);
        const __half2* p1 = reinterpret_cast<const __half2*>(h + (size_t)s1 * DHID + c);
        float2 a01 = __half22float2(p0[0]);
        float2 a23 = __half22float2(p0[1]);
        float2 b01 = __half22float2(p1[0]);
        float2 b23 = __half22float2(p1[1]);
        acc.x += c0 * a01.x + c1 * b01.x;
        acc.y += c0 * a01.y + c1 * b01.y;
        acc.z += c0 * a23.x + c1 * b23.x;
        acc.w += c0 * a23.y + c1 * b23.y;
    }
    if (e < end) {
        const int s0 = esrc[e];
        const float c0 = ecoef[e];
        const __half2* p0 = reinterpret_cast<const __half2*>(h + (size_t)s0 * DHID + c);
        float2 a01 = __half22float2(p0[0]);
        float2 a23 = __half22float2(p0[1]);
        acc.x += c0 * a01.x;
        acc.y += c0 * a01.y;
        acc.z += c0 * a23.x;
        acc.w += c0 * a23.y;
    }

    if (MODE == 2) {
        *reinterpret_cast<__half2*>(outfp16 + (size_t)node * DHID + c) =
            __floats2half2_rn(acc.x, acc.y);
        *reinterpret_cast<__half2*>(outfp16 + (size_t)node * DHID + c + 2) =
            __floats2half2_rn(acc.z, acc.w);
    } else {
        float v0 = fmaxf(acc.x, 0.f), v1 = fmaxf(acc.y, 0.f);
        float v2 = fmaxf(acc.z, 0.f), v3 = fmaxf(acc.w, 0.f);
        __nv_bfloat16 h0 = __float2bfloat16(v0);
        __nv_bfloat16 h1 = __float2bfloat16(v1);
        __nv_bfloat16 h2 = __float2bfloat16(v2);
        __nv_bfloat16 h3 = __float2bfloat16(v3);
        __nv_bfloat16 l0 = __float2bfloat16(v0 - __bfloat162float(h0));
        __nv_bfloat16 l1 = __float2bfloat16(v1 - __bfloat162float(h1));
        __nv_bfloat16 l2 = __float2bfloat16(v2 - __bfloat162float(h2));
        __nv_bfloat16 l3 = __float2bfloat16(v3 - __bfloat162float(h3));
        __nv_bfloat16* ph = outh + (size_t)node * DHID + c;
        __nv_bfloat16* pl = outl + (size_t)node * DHID + c;
        ph[0] = h0; ph[1] = h1; ph[2] = h2; ph[3] = h3;
        pl[0] = l0; pl[1] = l1; pl[2] = l2; pl[3] = l3;
    }
}

// ---------------------------------------------------------------------------
// Edge scoring from fp16 features (one warp per edge, fp32 accumulate).
// ---------------------------------------------------------------------------
__global__ __launch_bounds__(256)
void score_fp16_kernel(const __half* __restrict__ h,
                       const int* __restrict__ src,
                       const int* __restrict__ dst,
                       float* __restrict__ out, int e) {
    unsigned gt = blockIdx.x * blockDim.x + threadIdx.x;
    unsigned ed = gt >> 5;
    const int lane = threadIdx.x & 31;
    if (ed >= (unsigned)e) return;
    const int s = src[ed];
    const int d = dst[ed];
    uint4 su = *(reinterpret_cast<const uint4*>(h + (size_t)s * DHID) + lane);
    uint4 du = *(reinterpret_cast<const uint4*>(h + (size_t)d * DHID) + lane);
    const __half2* sv = reinterpret_cast<const __half2*>(&su);
    const __half2* dv = reinterpret_cast<const __half2*>(&du);
    float acc = 0.0f;
#pragma unroll
    for (int i = 0; i < 4; i++) {
        float2 a = __half22float2(sv[i]);
        float2 b = __half22float2(dv[i]);
        acc = fmaf(a.x, b.x, acc);
        acc = fmaf(a.y, b.y, acc);
    }
#pragma unroll
    for (int off = 16; off > 0; off >>= 1)
        acc += __shfl_xor_sync(0xFFFFFFFFu, acc, off);
    if (lane == 0) out[ed] = 1.0f / (1.0f + expf(-acc));
}

// ---------------------------------------------------------------------------
// Host launcher — CSR build forked onto a side stream
// ---------------------------------------------------------------------------
extern "C" void kernel_launch(void* const* d_in, const int* in_sizes, int n_in,
                              void* d_out, int out_size) {
    const float* x  = (const float*)d_in[0];
    const int*   ei = (const int*)d_in[1];
    const float* W1 = (const float*)d_in[2];
    const float* b1 = (const float*)d_in[3];
    const float* W2 = (const float*)d_in[4];
    const float* b2 = (const float*)d_in[5];
    float* out = (float*)d_out;

    const int N = in_sizes[0] / DIN;
    const int E = in_sizes[1] / 2;
    const int* src = ei;
    const int* dst = ei + E;

    int *p_cnt, *p_rowptr, *p_off, *p_esrc, *p_bsum, *p_boff;
    float *p_dinv, *p_ecoef;
    __half *p_h1, *p_h2, *p_agg2;
    __nv_bfloat16 *p_xh, *p_xl, *p_w1h, *p_w1l, *p_w2h, *p_w2l, *p_a1h, *p_a1l;
    cudaGetSymbolAddress((void**)&p_cnt,    g_cnt);
    cudaGetSymbolAddress((void**)&p_dinv,   g_dinv);
    cudaGetSymbolAddress((void**)&p_rowptr, g_rowptr);
    cudaGetSymbolAddress((void**)&p_off,    g_off);
    cudaGetSymbolAddress((void**)&p_bsum,   g_blocksum);
    cudaGetSymbolAddress((void**)&p_boff,   g_blockoff);
    cudaGetSymbolAddress((void**)&p_esrc,   g_esrc);
    cudaGetSymbolAddress((void**)&p_ecoef,  g_ecoef);
    cudaGetSymbolAddress((void**)&p_xh,     g_xh);
    cudaGetSymbolAddress((void**)&p_xl,     g_xl);
    cudaGetSymbolAddress((void**)&p_w1h,    g_w1h);
    cudaGetSymbolAddress((void**)&p_w1l,    g_w1l);
    cudaGetSymbolAddress((void**)&p_w2h,    g_w2h);
    cudaGetSymbolAddress((void**)&p_w2l,    g_w2l);
    cudaGetSymbolAddress((void**)&p_h1,     g_h1);
    cudaGetSymbolAddress((void**)&p_a1h,    g_a1h);
    cudaGetSymbolAddress((void**)&p_a1l,    g_a1l);
    cudaGetSymbolAddress((void**)&p_h2,     g_h2);
    cudaGetSymbolAddress((void**)&p_agg2,   g_agg2);

    static cudaStream_t s_side = nullptr;
    static cudaEvent_t  s_fork = nullptr, s_join = nullptr;
    if (s_side == nullptr) {
        cudaStreamCreateWithFlags(&s_side, cudaStreamNonBlocking);
        cudaEventCreateWithFlags(&s_fork, cudaEventDisableTiming);
        cudaEventCreateWithFlags(&s_join, cudaEventDisableTiming);
    }

    const int T = 256;

    // ---- fork: CSR build chain on side stream ----
    cudaEventRecord(s_fork, 0);
    cudaStreamWaitEvent(s_side, s_fork, 0);
    zero_cnt_kernel<<<(N + T - 1) / T, T, 0, s_side>>>(p_cnt, N);
    hist_kernel<<<(E + T - 1) / T, T, 0, s_side>>>(p_cnt, dst, E);
    dinv_kernel<<<(N + T - 1) / T, T, 0, s_side>>>(p_cnt, p_dinv, N);
    scan_p1_kernel<<<NB_SCAN, 256, 0, s_side>>>(p_cnt, p_bsum, N);
    scan_p2_kernel<<<1, NB_SCAN, 0, s_side>>>(p_bsum, p_boff, p_rowptr, N);
    scan_p3_kernel<<<NB_SCAN, 256, 0, s_side>>>(p_cnt, p_boff, p_rowptr, p_off, N);
    scatter_kernel<<<(E + T - 1) / T, T, 0, s_side>>>(src, dst, p_dinv, p_off,
                                                      p_esrc, p_ecoef, E);
    cudaEventRecord(s_join, s_side);

    // ---- main stream: splits + GEMM1 ----
    {
        int n4 = N * DIN / 4;
        split_kernel<<<(n4 + T - 1) / T, T>>>(x, p_xh, p_xl, n4);
        int w1n4 = DIN * DHID / 4;
        split_kernel<<<(w1n4 + T - 1) / T, T>>>(W1, p_w1h, p_w1l, w1n4);
        int w2n4 = DHID * DHID / 4;
        split_kernel<<<(w2n4 + T - 1) / T, T>>>(W2, p_w2h, p_w2l, w2n4);
    }
    {
        dim3 grid(DHID / 64, (N + 127) / 128);
        mma_gemm_pre_kernel<<<grid, 256>>>(p_xh, p_xl, p_w1h, p_w1l, p_h1, N, DIN, DHID);
    }

    // ---- join: agg1 needs CSR ----
    cudaStreamWaitEvent(0, s_join, 0);
    agg_csr_kernel<1><<<(N + 3) / 4, 256>>>(p_h1, b1, p_dinv, p_rowptr, p_esrc, p_ecoef,
                                            nullptr, p_a1h, p_a1l, N);

    {
        dim3 grid(DHID / 64, (N + 127) / 128);
        mma_gemm_pre_kernel<<<grid, 256>>>(p_a1h, p_a1l, p_w2h, p_w2l, p_h2, N, DHID, DHID);
    }
    agg_csr_kernel<2><<<(N + 3) / 4, 256>>>(p_h2, b2, p_dinv, p_rowptr, p_esrc, p_ecoef,
                                            p_agg2, nullptr, nullptr, N);

    // ---- edge scoring from fp16 ----
    score_fp16_kernel<<<((unsigned)E * 32 + T - 1) / T, T>>>(p_agg2, src, dst, out, E);
}

// round 12
// speedup vs baseline: 1.2418x; 1.0140x over previous
#include <cuda_runtime.h>
#include <cuda_bf16.h>
#include <cuda_fp16.h>
#include <stdint.h>
#include <math.h>

#define MAX_N 50000
#define MAX_E 800000
#define DHID 256
#define DIN 512
#define NB_SCAN 128

// Scratch device globals
__device__ int   g_cnt[MAX_N];
__device__ float g_dinv[MAX_N];
__device__ int   g_rowptr[MAX_N + 1];
__device__ int   g_off[MAX_N];
__device__ int   g_blocksum[NB_SCAN];
__device__ int   g_blockoff[NB_SCAN];
__device__ int   g_esrc[MAX_E];
__device__ float g_ecoef[MAX_E];

__device__ __nv_bfloat16 g_xh[(size_t)MAX_N * DIN];
__device__ __nv_bfloat16 g_xl[(size_t)MAX_N * DIN];
__device__ __nv_bfloat16 g_w1h[DIN * DHID];
__device__ __nv_bfloat16 g_w1l[DIN * DHID];
__device__ __nv_bfloat16 g_w2h[DHID * DHID];
__device__ __nv_bfloat16 g_w2l[DHID * DHID];
__device__ __half g_h1[(size_t)MAX_N * DHID];
__device__ __nv_bfloat16 g_a1h[(size_t)MAX_N * DHID];
__device__ __nv_bfloat16 g_a1l[(size_t)MAX_N * DHID];
__device__ __half g_h2[(size_t)MAX_N * DHID];
__device__ __half g_agg2[(size_t)MAX_N * DHID];

// ---------------------------------------------------------------------------
// CSR build
// ---------------------------------------------------------------------------
__global__ void zero_cnt_kernel(int* cnt, int n) {
    int i = blockIdx.x * blockDim.x + threadIdx.x;
    if (i < n) cnt[i] = 0;
}

__global__ void hist_kernel(int* cnt, const int* __restrict__ dst, int e) {
    int i = blockIdx.x * blockDim.x + threadIdx.x;
    if (i < e) atomicAdd(&cnt[dst[i]], 1);
}

__global__ void dinv_kernel(const int* __restrict__ cnt, float* __restrict__ dinv, int n) {
    int i = blockIdx.x * blockDim.x + threadIdx.x;
    if (i < n) dinv[i] = rsqrtf((float)(cnt[i] + 1));
}

__global__ __launch_bounds__(256)
void scan_p1_kernel(const int* __restrict__ cnt, int* __restrict__ blocksum, int n) {
    __shared__ int red[256];
    const int chunk = (n + NB_SCAN - 1) / NB_SCAN;
    const int beg = blockIdx.x * chunk;
    const int end = min(beg + chunk, n);
    int s = 0;
    for (int i = beg + threadIdx.x; i < end; i += 256) s += cnt[i];
    red[threadIdx.x] = s;
    __syncthreads();
    for (int d = 128; d > 0; d >>= 1) {
        if (threadIdx.x < d) red[threadIdx.x] += red[threadIdx.x + d];
        __syncthreads();
    }
    if (threadIdx.x == 0) blocksum[blockIdx.x] = red[0];
}

__global__ __launch_bounds__(NB_SCAN)
void scan_p2_kernel(const int* __restrict__ blocksum, int* __restrict__ blockoff,
                    int* __restrict__ rowptr, int n) {
    __shared__ int sh[NB_SCAN];
    const int t = threadIdx.x;
    sh[t] = blocksum[t];
    __syncthreads();
    for (int d = 1; d < NB_SCAN; d <<= 1) {
        int v = (t >= d) ? sh[t - d] : 0;
        __syncthreads();
        sh[t] += v;
        __syncthreads();
    }
    blockoff[t] = (t == 0) ? 0 : sh[t - 1];
    if (t == NB_SCAN - 1) rowptr[n] = sh[NB_SCAN - 1];
}

__global__ __launch_bounds__(256)
void scan_p3_kernel(const int* __restrict__ cnt, const int* __restrict__ blockoff,
                    int* __restrict__ rowptr, int* __restrict__ off, int n) {
    __shared__ int sh[256];
    const int chunk = (n + NB_SCAN - 1) / NB_SCAN;
    const int beg = blockIdx.x * chunk;
    const int end = min(beg + chunk, n);
    int running = blockoff[blockIdx.x];
    for (int base = beg; base < end; base += 256) {
        const int i = base + threadIdx.x;
        int v = (i < end) ? cnt[i] : 0;
        sh[threadIdx.x] = v;
        __syncthreads();
        for (int d = 1; d < 256; d <<= 1) {
            int t2 = (threadIdx.x >= d) ? sh[threadIdx.x - d] : 0;
            __syncthreads();
            sh[threadIdx.x] += t2;
            __syncthreads();
        }
        if (i < end) {
            const int excl = sh[threadIdx.x] - v;
            rowptr[i] = running + excl;
            off[i] = running + excl;
        }
        running += sh[255];
        __syncthreads();
    }
}

__global__ void scatter_kernel(const int* __restrict__ src, const int* __restrict__ dst,
                               const float* __restrict__ dinv, int* __restrict__ off,
                               int* __restrict__ esrc, float* __restrict__ ecoef, int e) {
    int i = blockIdx.x * blockDim.x + threadIdx.x;
    if (i < e) {
        const int s = src[i];
        const int d = dst[i];
        const int pos = atomicAdd(&off[d], 1);
        esrc[pos] = s;
        ecoef[pos] = dinv[s] * dinv[d];
    }
}

// ---------------------------------------------------------------------------
// fp32 -> (hi, lo) bf16 split
// ---------------------------------------------------------------------------
__global__ void split_kernel(const float* __restrict__ in,
                             __nv_bfloat16* __restrict__ hi,
                             __nv_bfloat16* __restrict__ lo, int n4) {
    int i = blockIdx.x * blockDim.x + threadIdx.x;
    if (i >= n4) return;
    float4 v = reinterpret_cast<const float4*>(in)[i];
    __nv_bfloat16 h0 = __float2bfloat16(v.x);
    __nv_bfloat16 h1 = __float2bfloat16(v.y);
    __nv_bfloat16 h2 = __float2bfloat16(v.z);
    __nv_bfloat16 h3 = __float2bfloat16(v.w);
    hi[i * 4 + 0] = h0; hi[i * 4 + 1] = h1; hi[i * 4 + 2] = h2; hi[i * 4 + 3] = h3;
    lo[i * 4 + 0] = __float2bfloat16(v.x - __bfloat162float(h0));
    lo[i * 4 + 1] = __float2bfloat16(v.y - __bfloat162float(h1));
    lo[i * 4 + 2] = __float2bfloat16(v.z - __bfloat162float(h2));
    lo[i * 4 + 3] = __float2bfloat16(v.w - __bfloat162float(h3));
}

// ---------------------------------------------------------------------------
// Tensor-core GEMM on pre-split bf16 operands (CTA 128x64, BK=16).
// Epilogue writes fp16.
// ---------------------------------------------------------------------------
#define A_PAD 24
#define B_PAD 72

__device__ __forceinline__ void ldsm_x4(uint32_t addr, uint32_t& r0, uint32_t& r1,
                                        uint32_t& r2, uint32_t& r3) {
    asm volatile("ldmatrix.sync.aligned.m8n8.x4.shared.b16 {%0,%1,%2,%3}, [%4];"
                 : "=r"(r0), "=r"(r1), "=r"(r2), "=r"(r3) : "r"(addr));
}
__device__ __forceinline__ void ldsm_x4_t(uint32_t addr, uint32_t& r0, uint32_t& r1,
                                          uint32_t& r2, uint32_t& r3) {
    asm volatile("ldmatrix.sync.aligned.m8n8.x4.trans.shared.b16 {%0,%1,%2,%3}, [%4];"
                 : "=r"(r0), "=r"(r1), "=r"(r2), "=r"(r3) : "r"(addr));
}
__device__ __forceinline__ void mma_bf16(float* d, const uint32_t* a, const uint32_t* b) {
    asm volatile("mma.sync.aligned.m16n8k16.row.col.f32.bf16.bf16.f32 "
                 "{%0,%1,%2,%3}, {%4,%5,%6,%7}, {%8,%9}, {%0,%1,%2,%3};"
                 : "+f"(d[0]), "+f"(d[1]), "+f"(d[2]), "+f"(d[3])
                 : "r"(a[0]), "r"(a[1]), "r"(a[2]), "r"(a[3]), "r"(b[0]), "r"(b[1]));
}
__device__ __forceinline__ void cp_async16(void* smem_dst, const void* gsrc, bool pred) {
    uint32_t saddr = (uint32_t)__cvta_generic_to_shared(smem_dst);
    int sz = pred ? 16 : 0;
    asm volatile("cp.async.cg.shared.global [%0], [%1], 16, %2;"
                 :: "r"(saddr), "l"(gsrc), "r"(sz));
}

__global__ __launch_bounds__(256)
void mma_gemm_pre_kernel(const __nv_bfloat16* __restrict__ Ahg,
                         const __nv_bfloat16* __restrict__ Alg,
                         const __nv_bfloat16* __restrict__ Bhg,
                         const __nv_bfloat16* __restrict__ Blg,
                         __half* __restrict__ C, int M, int K, int N) {
    __shared__ __nv_bfloat16 Ah[2][128][A_PAD];
    __shared__ __nv_bfloat16 Al[2][128][A_PAD];
    __shared__ __nv_bfloat16 Bh[2][16][B_PAD];
    __shared__ __nv_bfloat16 Bl[2][16][B_PAD];

    const int tid = threadIdx.x;
    const int wid = tid >> 5;
    const int lane = tid & 31;
    const int warp_m = wid & 3;
    const int warp_n = wid >> 2;
    const int rowBase = blockIdx.y * 128;
    const int colBase = blockIdx.x * 64;

    const int a_r = tid >> 1;
    const int a_k = (tid & 1) << 3;
    const int arow = rowBase + a_r;
    const bool a_ok = (arow < M);
    const int bt = tid & 127;
    const int b_r = bt >> 3;
    const int b_c = (bt & 7) << 3;
    const bool is_bh = (tid < 128);

    const int lrow = lane & 7;
    const int lmat = lane >> 3;
    const int a_mloc = ((lmat & 1) << 3) + lrow;
    const int a_khalf = lmat >> 1;
    const int b_krow = ((lmat & 1) << 3) + lrow;
    const int b_nhalf = lmat >> 1;

    float acc[2][4][4];
#pragma unroll
    for (int i = 0; i < 2; i++)
#pragma unroll
        for (int j = 0; j < 4; j++)
#pragma unroll
            for (int q = 0; q < 4; q++) acc[i][j][q] = 0.0f;

    const int KT = K >> 4;

    {
        cp_async16(&Ah[0][a_r][a_k], Ahg + (size_t)arow * K + a_k, a_ok);
        cp_async16(&Al[0][a_r][a_k], Alg + (size_t)arow * K + a_k, a_ok);
        if (is_bh)
            cp_async16(&Bh[0][b_r][b_c], Bhg + (size_t)b_r * N + colBase + b_c, true);
        else
            cp_async16(&Bl[0][b_r][b_c], Blg + (size_t)b_r * N + colBase + b_c, true);
        asm volatile("cp.async.commit_group;");
    }

    int buf = 0;
    for (int kt = 0; kt < KT; kt++) {
        asm volatile("cp.async.wait_group 0;");
        __syncthreads();

        if (kt + 1 < KT) {
            const int k0 = (kt + 1) << 4;
            const int nb = buf ^ 1;
            cp_async16(&Ah[nb][a_r][a_k], Ahg + (size_t)arow * K + k0 + a_k, a_ok);
            cp_async16(&Al[nb][a_r][a_k], Alg + (size_t)arow * K + k0 + a_k, a_ok);
            if (is_bh)
                cp_async16(&Bh[nb][b_r][b_c], Bhg + (size_t)(k0 + b_r) * N + colBase + b_c, true);
            else
                cp_async16(&Bl[nb][b_r][b_c], Blg + (size_t)(k0 + b_r) * N + colBase + b_c, true);
            asm volatile("cp.async.commit_group;");
        }

        uint32_t ah[2][4], al[2][4];
#pragma unroll
        for (int mf = 0; mf < 2; mf++) {
            const int m_base = warp_m * 32 + mf * 16;
            uint32_t addr_h = (uint32_t)__cvta_generic_to_shared(
                &Ah[buf][m_base + a_mloc][a_khalf * 8]);
            ldsm_x4(addr_h, ah[mf][0], ah[mf][1], ah[mf][2], ah[mf][3]);
            uint32_t addr_l = (uint32_t)__cvta_generic_to_shared(
                &Al[buf][m_base + a_mloc][a_khalf * 8]);
            ldsm_x4(addr_l, al[mf][0], al[mf][1], al[mf][2], al[mf][3]);
        }
        uint32_t bh[2][4], bl[2][4];
#pragma unroll
        for (int g = 0; g < 2; g++) {
            const int n_base = warp_n * 32 + g * 16;
            uint32_t addr_h = (uint32_t)__cvta_generic_to_shared(
                &Bh[buf][b_krow][n_base + b_nhalf * 8]);
            ldsm_x4_t(addr_h, bh[g][0], bh[g][1], bh[g][2], bh[g][3]);
            uint32_t addr_l = (uint32_t)__cvta_generic_to_shared(
                &Bl[buf][b_krow][n_base + b_nhalf * 8]);
            ldsm_x4_t(addr_l, bl[g][0], bl[g][1], bl[g][2], bl[g][3]);
        }
#pragma unroll
        for (int mf = 0; mf < 2; mf++) {
#pragma unroll
            for (int g = 0; g < 2; g++) {
#pragma unroll
                for (int h = 0; h < 2; h++) {
                    float* d = acc[mf][g * 2 + h];
                    const uint32_t bhp[2] = {bh[g][h * 2], bh[g][h * 2 + 1]};
                    const uint32_t blp[2] = {bl[g][h * 2], bl[g][h * 2 + 1]};
                    mma_bf16(d, ah[mf], bhp);
                    mma_bf16(d, ah[mf], blp);
                    mma_bf16(d, al[mf], bhp);
                }
            }
        }
        buf ^= 1;
    }

    const int lq = lane >> 2;
    const int lr = lane & 3;
#pragma unroll
    for (int mf = 0; mf < 2; mf++) {
#pragma unroll
        for (int g = 0; g < 2; g++) {
#pragma unroll
            for (int h = 0; h < 2; h++) {
                const float* d = acc[mf][g * 2 + h];
                const int col = colBase + warp_n * 32 + g * 16 + h * 8 + lr * 2;
                const int r0 = rowBase + warp_m * 32 + mf * 16 + lq;
                if (r0 < M)
                    *reinterpret_cast<__half2*>(C + (size_t)r0 * N + col) =
                        __floats2half2_rn(d[0], d[1]);
                const int r1 = r0 + 8;
                if (r1 < M)
                    *reinterpret_cast<__half2*>(C + (size_t)r1 * N + col) =
                        __floats2half2_rn(d[2], d[3]);
            }
        }
    }
}

// ---------------------------------------------------------------------------
// CSR aggregation from fp16 h; 4-edge unrolled gather loop for MLP.
// MODE 1: relu + bf16 split write. MODE 2: fp16 write.
// ---------------------------------------------------------------------------
template <int MODE>
__global__ __launch_bounds__(256)
void agg_csr_kernel(const __half* __restrict__ h, const float* __restrict__ bias,
                    const float* __restrict__ dinv,
                    const int* __restrict__ rowptr, const int* __restrict__ esrc,
                    const float* __restrict__ ecoef,
                    __half* __restrict__ outfp16,
                    __nv_bfloat16* __restrict__ outh,
                    __nv_bfloat16* __restrict__ outl, int n) {
    const int node = blockIdx.x * 4 + (threadIdx.x >> 6);
    if (node >= n) return;
    const int c = (threadIdx.x & 63) << 2;

    const float di = dinv[node];
    const float wself = di * di;
    const __half2* hp = reinterpret_cast<const __half2*>(h + (size_t)node * DHID + c);
    float2 h01 = __half22float2(hp[0]);
    float2 h23 = __half22float2(hp[1]);
    float4 bb = *reinterpret_cast<const float4*>(bias + c);
    float4 acc;
    acc.x = fmaf(h01.x, wself, bb.x);
    acc.y = fmaf(h01.y, wself, bb.y);
    acc.z = fmaf(h23.x, wself, bb.z);
    acc.w = fmaf(h23.y, wself, bb.w);

    const int beg = rowptr[node];
    const int end = rowptr[node + 1];
    int e = beg;

    // 4-edge unroll: 8 independent 8B loads in flight per iteration
    for (; e + 4 <= end; e += 4) {
        const int s0 = esrc[e + 0];
        const int s1 = esrc[e + 1];
        const int s2 = esrc[e + 2];
        const int s3 = esrc[e + 3];
        const float c0 = ecoef[e + 0];
        const float c1 = ecoef[e + 1];
        const float c2 = ecoef[e + 2];
        const float c3 = ecoef[e + 3];
        const __half2* p0 = reinterpret_cast<const __half2*>(h + (size_t)s0 * DHID + c);
        const __half2* p1 = reinterpret_cast<const __half2*>(h + (size_t)s1 * DHID + c);
        const __half2* p2 = reinterpret_cast<const __half2*>(h + (size_t)s2 * DHID + c);
        const __half2* p3 = reinterpret_cast<const __half2*>(h + (size_t)s3 * DHID + c);
        __half2 v0a = p0[0], v0b = p0[1];
        __half2 v1a = p1[0], v1b = p1[1];
        __half2 v2a = p2[0], v2b = p2[1];
        __half2 v3a = p3[0], v3b = p3[1];
        float2 a0a = __half22float2(v0a), a0b = __half22float2(v0b);
        float2 a1a = __half22float2(v1a), a1b = __half22float2(v1b);
        float2 a2a = __half22float2(v2a), a2b = __half22float2(v2b);
        float2 a3a = __half22float2(v3a), a3b = __half22float2(v3b);
        acc.x += c0 * a0a.x + c1 * a1a.x + c2 * a2a.x + c3 * a3a.x;
        acc.y += c0 * a0a.y + c1 * a1a.y + c2 * a2a.y + c3 * a3a.y;
        acc.z += c0 * a0b.x + c1 * a1b.x + c2 * a2b.x + c3 * a3b.x;
        acc.w += c0 * a0b.y + c1 * a1b.y + c2 * a2b.y + c3 * a3b.y;
    }
    for (; e < end; e++) {
        const int s0 = esrc[e];
        const float c0 = ecoef[e];
        const __half2* p0 = reinterpret_cast<const __half2*>(h + (size_t)s0 * DHID + c);
        float2 a01 = __half22float2(p0[0]);
        float2 a23 = __half22float2(p0[1]);
        acc.x += c0 * a01.x;
        acc.y += c0 * a01.y;
        acc.z += c0 * a23.x;
        acc.w += c0 * a23.y;
    }

    if (MODE == 2) {
        *reinterpret_cast<__half2*>(outfp16 + (size_t)node * DHID + c) =
            __floats2half2_rn(acc.x, acc.y);
        *reinterpret_cast<__half2*>(outfp16 + (size_t)node * DHID + c + 2) =
            __floats2half2_rn(acc.z, acc.w);
    } else {
        float v0 = fmaxf(acc.x, 0.f), v1 = fmaxf(acc.y, 0.f);
        float v2 = fmaxf(acc.z, 0.f), v3 = fmaxf(acc.w, 0.f);
        __nv_bfloat16 h0 = __float2bfloat16(v0);
        __nv_bfloat16 h1 = __float2bfloat16(v1);
        __nv_bfloat16 h2 = __float2bfloat16(v2);
        __nv_bfloat16 h3 = __float2bfloat16(v3);
        __nv_bfloat16 l0 = __float2bfloat16(v0 - __bfloat162float(h0));
        __nv_bfloat16 l1 = __float2bfloat16(v1 - __bfloat162float(h1));
        __nv_bfloat16 l2 = __float2bfloat16(v2 - __bfloat162float(h2));
        __nv_bfloat16 l3 = __float2bfloat16(v3 - __bfloat162float(h3));
        __nv_bfloat16* ph = outh + (size_t)node * DHID + c;
        __nv_bfloat16* pl = outl + (size_t)node * DHID + c;
        ph[0] = h0; ph[1] = h1; ph[2] = h2; ph[3] = h3;
        pl[0] = l0; pl[1] = l1; pl[2] = l2; pl[3] = l3;
    }
}

// ---------------------------------------------------------------------------
// Edge scoring from fp16 features (one warp per edge, fp32 accumulate).
// ---------------------------------------------------------------------------
__global__ __launch_bounds__(256)
void score_fp16_kernel(const __half* __restrict__ h,
                       const int* __restrict__ src,
                       const int* __restrict__ dst,
                       float* __restrict__ out, int e) {
    unsigned gt = blockIdx.x * blockDim.x + threadIdx.x;
    unsigned ed = gt >> 5;
    const int lane = threadIdx.x & 31;
    if (ed >= (unsigned)e) return;
    const int s = src[ed];
    const int d = dst[ed];
    uint4 su = *(reinterpret_cast<const uint4*>(h + (size_t)s * DHID) + lane);
    uint4 du = *(reinterpret_cast<const uint4*>(h + (size_t)d * DHID) + lane);
    const __half2* sv = reinterpret_cast<const __half2*>(&su);
    const __half2* dv = reinterpret_cast<const __half2*>(&du);
    float acc = 0.0f;
#pragma unroll
    for (int i = 0; i < 4; i++) {
        float2 a = __half22float2(sv[i]);
        float2 b = __half22float2(dv[i]);
        acc = fmaf(a.x, b.x, acc);
        acc = fmaf(a.y, b.y, acc);
    }
#pragma unroll
    for (int off = 16; off > 0; off >>= 1)
        acc += __shfl_xor_sync(0xFFFFFFFFu, acc, off);
    if (lane == 0) out[ed] = 1.0f / (1.0f + expf(-acc));
}

// ---------------------------------------------------------------------------
// Host launcher — CSR build forked onto a side stream
// ---------------------------------------------------------------------------
extern "C" void kernel_launch(void* const* d_in, const int* in_sizes, int n_in,
                              void* d_out, int out_size) {
    const float* x  = (const float*)d_in[0];
    const int*   ei = (const int*)d_in[1];
    const float* W1 = (const float*)d_in[2];
    const float* b1 = (const float*)d_in[3];
    const float* W2 = (const float*)d_in[4];
    const float* b2 = (const float*)d_in[5];
    float* out = (float*)d_out;

    const int N = in_sizes[0] / DIN;
    const int E = in_sizes[1] / 2;
    const int* src = ei;
    const int* dst = ei + E;

    int *p_cnt, *p_rowptr, *p_off, *p_esrc, *p_bsum, *p_boff;
    float *p_dinv, *p_ecoef;
    __half *p_h1, *p_h2, *p_agg2;
    __nv_bfloat16 *p_xh, *p_xl, *p_w1h, *p_w1l, *p_w2h, *p_w2l, *p_a1h, *p_a1l;
    cudaGetSymbolAddress((void**)&p_cnt,    g_cnt);
    cudaGetSymbolAddress((void**)&p_dinv,   g_dinv);
    cudaGetSymbolAddress((void**)&p_rowptr, g_rowptr);
    cudaGetSymbolAddress((void**)&p_off,    g_off);
    cudaGetSymbolAddress((void**)&p_bsum,   g_blocksum);
    cudaGetSymbolAddress((void**)&p_boff,   g_blockoff);
    cudaGetSymbolAddress((void**)&p_esrc,   g_esrc);
    cudaGetSymbolAddress((void**)&p_ecoef,  g_ecoef);
    cudaGetSymbolAddress((void**)&p_xh,     g_xh);
    cudaGetSymbolAddress((void**)&p_xl,     g_xl);
    cudaGetSymbolAddress((void**)&p_w1h,    g_w1h);
    cudaGetSymbolAddress((void**)&p_w1l,    g_w1l);
    cudaGetSymbolAddress((void**)&p_w2h,    g_w2h);
    cudaGetSymbolAddress((void**)&p_w2l,    g_w2l);
    cudaGetSymbolAddress((void**)&p_h1,     g_h1);
    cudaGetSymbolAddress((void**)&p_a1h,    g_a1h);
    cudaGetSymbolAddress((void**)&p_a1l,    g_a1l);
    cudaGetSymbolAddress((void**)&p_h2,     g_h2);
    cudaGetSymbolAddress((void**)&p_agg2,   g_agg2);

    static cudaStream_t s_side = nullptr;
    static cudaEvent_t  s_fork = nullptr, s_join = nullptr;
    if (s_side == nullptr) {
        cudaStreamCreateWithFlags(&s_side, cudaStreamNonBlocking);
        cudaEventCreateWithFlags(&s_fork, cudaEventDisableTiming);
        cudaEventCreateWithFlags(&s_join, cudaEventDisableTiming);
    }

    const int T = 256;

    // ---- fork: CSR build chain on side stream ----
    cudaEventRecord(s_fork, 0);
    cudaStreamWaitEvent(s_side, s_fork, 0);
    zero_cnt_kernel<<<(N + T - 1) / T, T, 0, s_side>>>(p_cnt, N);
    hist_kernel<<<(E + T - 1) / T, T, 0, s_side>>>(p_cnt, dst, E);
    dinv_kernel<<<(N + T - 1) / T, T, 0, s_side>>>(p_cnt, p_dinv, N);
    scan_p1_kernel<<<NB_SCAN, 256, 0, s_side>>>(p_cnt, p_bsum, N);
    scan_p2_kernel<<<1, NB_SCAN, 0, s_side>>>(p_bsum, p_boff, p_rowptr, N);
    scan_p3_kernel<<<NB_SCAN, 256, 0, s_side>>>(p_cnt, p_boff, p_rowptr, p_off, N);
    scatter_kernel<<<(E + T - 1) / T, T, 0, s_side>>>(src, dst, p_dinv, p_off,
                                                      p_esrc, p_ecoef, E);
    cudaEventRecord(s_join, s_side);

    // ---- main stream: splits + GEMM1 ----
    {
        int n4 = N * DIN / 4;
        split_kernel<<<(n4 + T - 1) / T, T>>>(x, p_xh, p_xl, n4);
        int w1n4 = DIN * DHID / 4;
        split_kernel<<<(w1n4 + T - 1) / T, T>>>(W1, p_w1h, p_w1l, w1n4);
        int w2n4 = DHID * DHID / 4;
        split_kernel<<<(w2n4 + T - 1) / T, T>>>(W2, p_w2h, p_w2l, w2n4);
    }
    {
        dim3 grid(DHID / 64, (N + 127) / 128);
        mma_gemm_pre_kernel<<<grid, 256>>>(p_xh, p_xl, p_w1h, p_w1l, p_h1, N, DIN, DHID);
    }

    // ---- join: agg1 needs CSR ----
    cudaStreamWaitEvent(0, s_join, 0);
    agg_csr_kernel<1><<<(N + 3) / 4, 256>>>(p_h1, b1, p_dinv, p_rowptr, p_esrc, p_ecoef,
                                            nullptr, p_a1h, p_a1l, N);

    {
        dim3 grid(DHID / 64, (N + 127) / 128);
        mma_gemm_pre_kernel<<<grid, 256>>>(p_a1h, p_a1l, p_w2h, p_w2l, p_h2, N, DHID, DHID);
    }
    agg_csr_kernel<2><<<(N + 3) / 4, 256>>>(p_h2, b2, p_dinv, p_rowptr, p_esrc, p_ecoef,
                                            p_agg2, nullptr, nullptr, N);

    // ---- edge scoring from fp16 ----
    score_fp16_kernel<<<((unsigned)E * 32 + T - 1) / T, T>>>(p_agg2, src, dst, out, E);
}

// round 13
// speedup vs baseline: 1.2795x; 1.0304x over previous
#include <cuda_runtime.h>
#include <cuda_bf16.h>
#include <cuda_fp16.h>
#include <stdint.h>
#include <math.h>

#define MAX_N 50000
#define MAX_E 800000
#define DHID 256
#define DIN 512
#define NB_SCAN 128

// Scratch device globals
__device__ int   g_cnt[MAX_N];
__device__ float g_dinv[MAX_N];
__device__ int   g_rowptr[MAX_N + 1];
__device__ int   g_off[MAX_N];
__device__ int   g_blocksum[NB_SCAN];
__device__ int   g_blockoff[NB_SCAN];
__device__ int   g_esrc[MAX_E];
__device__ float g_ecoef[MAX_E];

__device__ __nv_bfloat16 g_xh[(size_t)MAX_N * DIN];
__device__ __nv_bfloat16 g_xl[(size_t)MAX_N * DIN];
__device__ __nv_bfloat16 g_w1h[DIN * DHID];
__device__ __nv_bfloat16 g_w1l[DIN * DHID];
__device__ __nv_bfloat16 g_w2h[DHID * DHID];
__device__ __nv_bfloat16 g_w2l[DHID * DHID];
__device__ __half g_h1[(size_t)MAX_N * DHID];
__device__ __nv_bfloat16 g_a1h[(size_t)MAX_N * DHID];
__device__ __nv_bfloat16 g_a1l[(size_t)MAX_N * DHID];
__device__ __half g_h2[(size_t)MAX_N * DHID];
__device__ __half g_agg2[(size_t)MAX_N * DHID];

// ---------------------------------------------------------------------------
// CSR build
// ---------------------------------------------------------------------------
__global__ void zero_cnt_kernel(int* cnt, int n) {
    int i = blockIdx.x * blockDim.x + threadIdx.x;
    if (i < n) cnt[i] = 0;
}

__global__ void hist_kernel(int* cnt, const int* __restrict__ dst, int e) {
    int i = blockIdx.x * blockDim.x + threadIdx.x;
    if (i < e) atomicAdd(&cnt[dst[i]], 1);
}

__global__ void dinv_kernel(const int* __restrict__ cnt, float* __restrict__ dinv, int n) {
    int i = blockIdx.x * blockDim.x + threadIdx.x;
    if (i < n) dinv[i] = rsqrtf((float)(cnt[i] + 1));
}

__global__ __launch_bounds__(256)
void scan_p1_kernel(const int* __restrict__ cnt, int* __restrict__ blocksum, int n) {
    __shared__ int red[256];
    const int chunk = (n + NB_SCAN - 1) / NB_SCAN;
    const int beg = blockIdx.x * chunk;
    const int end = min(beg + chunk, n);
    int s = 0;
    for (int i = beg + threadIdx.x; i < end; i += 256) s += cnt[i];
    red[threadIdx.x] = s;
    __syncthreads();
    for (int d = 128; d > 0; d >>= 1) {
        if (threadIdx.x < d) red[threadIdx.x] += red[threadIdx.x + d];
        __syncthreads();
    }
    if (threadIdx.x == 0) blocksum[blockIdx.x] = red[0];
}

__global__ __launch_bounds__(NB_SCAN)
void scan_p2_kernel(const int* __restrict__ blocksum, int* __restrict__ blockoff,
                    int* __restrict__ rowptr, int n) {
    __shared__ int sh[NB_SCAN];
    const int t = threadIdx.x;
    sh[t] = blocksum[t];
    __syncthreads();
    for (int d = 1; d < NB_SCAN; d <<= 1) {
        int v = (t >= d) ? sh[t - d] : 0;
        __syncthreads();
        sh[t] += v;
        __syncthreads();
    }
    blockoff[t] = (t == 0) ? 0 : sh[t - 1];
    if (t == NB_SCAN - 1) rowptr[n] = sh[NB_SCAN - 1];
}

__global__ __launch_bounds__(256)
void scan_p3_kernel(const int* __restrict__ cnt, const int* __restrict__ blockoff,
                    int* __restrict__ rowptr, int* __restrict__ off, int n) {
    __shared__ int sh[256];
    const int chunk = (n + NB_SCAN - 1) / NB_SCAN;
    const int beg = blockIdx.x * chunk;
    const int end = min(beg + chunk, n);
    int running = blockoff[blockIdx.x];
    for (int base = beg; base < end; base += 256) {
        const int i = base + threadIdx.x;
        int v = (i < end) ? cnt[i] : 0;
        sh[threadIdx.x] = v;
        __syncthreads();
        for (int d = 1; d < 256; d <<= 1) {
            int t2 = (threadIdx.x >= d) ? sh[threadIdx.x - d] : 0;
            __syncthreads();
            sh[threadIdx.x] += t2;
            __syncthreads();
        }
        if (i < end) {
            const int excl = sh[threadIdx.x] - v;
            rowptr[i] = running + excl;
            off[i] = running + excl;
        }
        running += sh[255];
        __syncthreads();
    }
}

__global__ void scatter_kernel(const int* __restrict__ src, const int* __restrict__ dst,
                               const float* __restrict__ dinv, int* __restrict__ off,
                               int* __restrict__ esrc, float* __restrict__ ecoef, int e) {
    int i = blockIdx.x * blockDim.x + threadIdx.x;
    if (i < e) {
        const int s = src[i];
        const int d = dst[i];
        const int pos = atomicAdd(&off[d], 1);
        esrc[pos] = s;
        ecoef[pos] = dinv[s] * dinv[d];
    }
}

// ---------------------------------------------------------------------------
// fp32 -> (hi, lo) bf16 split
// ---------------------------------------------------------------------------
__global__ void split_kernel(const float* __restrict__ in,
                             __nv_bfloat16* __restrict__ hi,
                             __nv_bfloat16* __restrict__ lo, int n4) {
    int i = blockIdx.x * blockDim.x + threadIdx.x;
    if (i >= n4) return;
    float4 v = reinterpret_cast<const float4*>(in)[i];
    __nv_bfloat16 h0 = __float2bfloat16(v.x);
    __nv_bfloat16 h1 = __float2bfloat16(v.y);
    __nv_bfloat16 h2 = __float2bfloat16(v.z);
    __nv_bfloat16 h3 = __float2bfloat16(v.w);
    hi[i * 4 + 0] = h0; hi[i * 4 + 1] = h1; hi[i * 4 + 2] = h2; hi[i * 4 + 3] = h3;
    lo[i * 4 + 0] = __float2bfloat16(v.x - __bfloat162float(h0));
    lo[i * 4 + 1] = __float2bfloat16(v.y - __bfloat162float(h1));
    lo[i * 4 + 2] = __float2bfloat16(v.z - __bfloat162float(h2));
    lo[i * 4 + 3] = __float2bfloat16(v.w - __bfloat162float(h3));
}

// ---------------------------------------------------------------------------
// Tensor-core GEMM on pre-split bf16 operands (CTA 128x64, BK=16).
// Epilogue writes fp16.
// ---------------------------------------------------------------------------
#define A_PAD 24
#define B_PAD 72

__device__ __forceinline__ void ldsm_x4(uint32_t addr, uint32_t& r0, uint32_t& r1,
                                        uint32_t& r2, uint32_t& r3) {
    asm volatile("ldmatrix.sync.aligned.m8n8.x4.shared.b16 {%0,%1,%2,%3}, [%4];"
                 : "=r"(r0), "=r"(r1), "=r"(r2), "=r"(r3) : "r"(addr));
}
__device__ __forceinline__ void ldsm_x4_t(uint32_t addr, uint32_t& r0, uint32_t& r1,
                                          uint32_t& r2, uint32_t& r3) {
    asm volatile("ldmatrix.sync.aligned.m8n8.x4.trans.shared.b16 {%0,%1,%2,%3}, [%4];"
                 : "=r"(r0), "=r"(r1), "=r"(r2), "=r"(r3) : "r"(addr));
}
__device__ __forceinline__ void mma_bf16(float* d, const uint32_t* a, const uint32_t* b) {
    asm volatile("mma.sync.aligned.m16n8k16.row.col.f32.bf16.bf16.f32 "
                 "{%0,%1,%2,%3}, {%4,%5,%6,%7}, {%8,%9}, {%0,%1,%2,%3};"
                 : "+f"(d[0]), "+f"(d[1]), "+f"(d[2]), "+f"(d[3])
                 : "r"(a[0]), "r"(a[1]), "r"(a[2]), "r"(a[3]), "r"(b[0]), "r"(b[1]));
}
__device__ __forceinline__ void cp_async16(void* smem_dst, const void* gsrc, bool pred) {
    uint32_t saddr = (uint32_t)__cvta_generic_to_shared(smem_dst);
    int sz = pred ? 16 : 0;
    asm volatile("cp.async.cg.shared.global [%0], [%1], 16, %2;"
                 :: "r"(saddr), "l"(gsrc), "r"(sz));
}

__global__ __launch_bounds__(256)
void mma_gemm_pre_kernel(const __nv_bfloat16* __restrict__ Ahg,
                         const __nv_bfloat16* __restrict__ Alg,
                         const __nv_bfloat16* __restrict__ Bhg,
                         const __nv_bfloat16* __restrict__ Blg,
                         __half* __restrict__ C, int M, int K, int N) {
    __shared__ __nv_bfloat16 Ah[2][128][A_PAD];
    __shared__ __nv_bfloat16 Al[2][128][A_PAD];
    __shared__ __nv_bfloat16 Bh[2][16][B_PAD];
    __shared__ __nv_bfloat16 Bl[2][16][B_PAD];

    const int tid = threadIdx.x;
    const int wid = tid >> 5;
    const int lane = tid & 31;
    const int warp_m = wid & 3;
    const int warp_n = wid >> 2;
    const int rowBase = blockIdx.y * 128;
    const int colBase = blockIdx.x * 64;

    const int a_r = tid >> 1;
    const int a_k = (tid & 1) << 3;
    const int arow = rowBase + a_r;
    const bool a_ok = (arow < M);
    const int bt = tid & 127;
    const int b_r = bt >> 3;
    const int b_c = (bt & 7) << 3;
    const bool is_bh = (tid < 128);

    const int lrow = lane & 7;
    const int lmat = lane >> 3;
    const int a_mloc = ((lmat & 1) << 3) + lrow;
    const int a_khalf = lmat >> 1;
    const int b_krow = ((lmat & 1) << 3) + lrow;
    const int b_nhalf = lmat >> 1;

    float acc[2][4][4];
#pragma unroll
    for (int i = 0; i < 2; i++)
#pragma unroll
        for (int j = 0; j < 4; j++)
#pragma unroll
            for (int q = 0; q < 4; q++) acc[i][j][q] = 0.0f;

    const int KT = K >> 4;

    {
        cp_async16(&Ah[0][a_r][a_k], Ahg + (size_t)arow * K + a_k, a_ok);
        cp_async16(&Al[0][a_r][a_k], Alg + (size_t)arow * K + a_k, a_ok);
        if (is_bh)
            cp_async16(&Bh[0][b_r][b_c], Bhg + (size_t)b_r * N + colBase + b_c, true);
        else
            cp_async16(&Bl[0][b_r][b_c], Blg + (size_t)b_r * N + colBase + b_c, true);
        asm volatile("cp.async.commit_group;");
    }

    int buf = 0;
    for (int kt = 0; kt < KT; kt++) {
        asm volatile("cp.async.wait_group 0;");
        __syncthreads();

        if (kt + 1 < KT) {
            const int k0 = (kt + 1) << 4;
            const int nb = buf ^ 1;
            cp_async16(&Ah[nb][a_r][a_k], Ahg + (size_t)arow * K + k0 + a_k, a_ok);
            cp_async16(&Al[nb][a_r][a_k], Alg + (size_t)arow * K + k0 + a_k, a_ok);
            if (is_bh)
                cp_async16(&Bh[nb][b_r][b_c], Bhg + (size_t)(k0 + b_r) * N + colBase + b_c, true);
            else
                cp_async16(&Bl[nb][b_r][b_c], Blg + (size_t)(k0 + b_r) * N + colBase + b_c, true);
            asm volatile("cp.async.commit_group;");
        }

        uint32_t ah[2][4], al[2][4];
#pragma unroll
        for (int mf = 0; mf < 2; mf++) {
            const int m_base = warp_m * 32 + mf * 16;
            uint32_t addr_h = (uint32_t)__cvta_generic_to_shared(
                &Ah[buf][m_base + a_mloc][a_khalf * 8]);
            ldsm_x4(addr_h, ah[mf][0], ah[mf][1], ah[mf][2], ah[mf][3]);
            uint32_t addr_l = (uint32_t)__cvta_generic_to_shared(
                &Al[buf][m_base + a_mloc][a_khalf * 8]);
            ldsm_x4(addr_l, al[mf][0], al[mf][1], al[mf][2], al[mf][3]);
        }
        uint32_t bh[2][4], bl[2][4];
#pragma unroll
        for (int g = 0; g < 2; g++) {
            const int n_base = warp_n * 32 + g * 16;
            uint32_t addr_h = (uint32_t)__cvta_generic_to_shared(
                &Bh[buf][b_krow][n_base + b_nhalf * 8]);
            ldsm_x4_t(addr_h, bh[g][0], bh[g][1], bh[g][2], bh[g][3]);
            uint32_t addr_l = (uint32_t)__cvta_generic_to_shared(
                &Bl[buf][b_krow][n_base + b_nhalf * 8]);
            ldsm_x4_t(addr_l, bl[g][0], bl[g][1], bl[g][2], bl[g][3]);
        }
#pragma unroll
        for (int mf = 0; mf < 2; mf++) {
#pragma unroll
            for (int g = 0; g < 2; g++) {
#pragma unroll
                for (int h = 0; h < 2; h++) {
                    float* d = acc[mf][g * 2 + h];
                    const uint32_t bhp[2] = {bh[g][h * 2], bh[g][h * 2 + 1]};
                    const uint32_t blp[2] = {bl[g][h * 2], bl[g][h * 2 + 1]};
                    mma_bf16(d, ah[mf], bhp);
                    mma_bf16(d, ah[mf], blp);
                    mma_bf16(d, al[mf], bhp);
                }
            }
        }
        buf ^= 1;
    }

    const int lq = lane >> 2;
    const int lr = lane & 3;
#pragma unroll
    for (int mf = 0; mf < 2; mf++) {
#pragma unroll
        for (int g = 0; g < 2; g++) {
#pragma unroll
            for (int h = 0; h < 2; h++) {
                const float* d = acc[mf][g * 2 + h];
                const int col = colBase + warp_n * 32 + g * 16 + h * 8 + lr * 2;
                const int r0 = rowBase + warp_m * 32 + mf * 16 + lq;
                if (r0 < M)
                    *reinterpret_cast<__half2*>(C + (size_t)r0 * N + col) =
                        __floats2half2_rn(d[0], d[1]);
                const int r1 = r0 + 8;
                if (r1 < M)
                    *reinterpret_cast<__half2*>(C + (size_t)r1 * N + col) =
                        __floats2half2_rn(d[2], d[3]);
            }
        }
    }
}

// ---------------------------------------------------------------------------
// CSR aggregation from fp16 h — 32 threads/node, 8 dims (16B) per thread,
// 4-edge unroll (4x16B gathers in flight). fp32 accumulate.
// MODE 1: relu + bf16 split write. MODE 2: fp16 write.
// ---------------------------------------------------------------------------
__device__ __forceinline__ void acc8_add(float* acc, const uint4& v, float cc) {
    const __half2* p = reinterpret_cast<const __half2*>(&v);
#pragma unroll
    for (int i = 0; i < 4; i++) {
        float2 f = __half22float2(p[i]);
        acc[2 * i + 0] = fmaf(cc, f.x, acc[2 * i + 0]);
        acc[2 * i + 1] = fmaf(cc, f.y, acc[2 * i + 1]);
    }
}

template <int MODE>
__global__ __launch_bounds__(256)
void agg_csr_kernel(const __half* __restrict__ h, const float* __restrict__ bias,
                    const float* __restrict__ dinv,
                    const int* __restrict__ rowptr, const int* __restrict__ esrc,
                    const float* __restrict__ ecoef,
                    __half* __restrict__ outfp16,
                    __nv_bfloat16* __restrict__ outh,
                    __nv_bfloat16* __restrict__ outl, int n) {
    const int node = blockIdx.x * 8 + (threadIdx.x >> 5);
    if (node >= n) return;
    const int c = (threadIdx.x & 31) << 3;   // 8 dims per thread

    const float di = dinv[node];
    const float ws = di * di;
    float acc[8];
    {
        uint4 hv = *reinterpret_cast<const uint4*>(h + (size_t)node * DHID + c);
        const __half2* hh = reinterpret_cast<const __half2*>(&hv);
        float4 b0 = *reinterpret_cast<const float4*>(bias + c);
        float4 b1 = *reinterpret_cast<const float4*>(bias + c + 4);
        float2 f;
        f = __half22float2(hh[0]); acc[0] = fmaf(f.x, ws, b0.x); acc[1] = fmaf(f.y, ws, b0.y);
        f = __half22float2(hh[1]); acc[2] = fmaf(f.x, ws, b0.z); acc[3] = fmaf(f.y, ws, b0.w);
        f = __half22float2(hh[2]); acc[4] = fmaf(f.x, ws, b1.x); acc[5] = fmaf(f.y, ws, b1.y);
        f = __half22float2(hh[3]); acc[6] = fmaf(f.x, ws, b1.z); acc[7] = fmaf(f.y, ws, b1.w);
    }

    const int beg = rowptr[node];
    const int end = rowptr[node + 1];
    int e = beg;
    for (; e + 4 <= end; e += 4) {
        const int s0 = esrc[e + 0];
        const int s1 = esrc[e + 1];
        const int s2 = esrc[e + 2];
        const int s3 = esrc[e + 3];
        const float c0 = ecoef[e + 0];
        const float c1 = ecoef[e + 1];
        const float c2 = ecoef[e + 2];
        const float c3 = ecoef[e + 3];
        uint4 v0 = *reinterpret_cast<const uint4*>(h + (size_t)s0 * DHID + c);
        uint4 v1 = *reinterpret_cast<const uint4*>(h + (size_t)s1 * DHID + c);
        uint4 v2 = *reinterpret_cast<const uint4*>(h + (size_t)s2 * DHID + c);
        uint4 v3 = *reinterpret_cast<const uint4*>(h + (size_t)s3 * DHID + c);
        acc8_add(acc, v0, c0);
        acc8_add(acc, v1, c1);
        acc8_add(acc, v2, c2);
        acc8_add(acc, v3, c3);
    }
    for (; e < end; e++) {
        const int s0 = esrc[e];
        const float c0 = ecoef[e];
        uint4 v0 = *reinterpret_cast<const uint4*>(h + (size_t)s0 * DHID + c);
        acc8_add(acc, v0, c0);
    }

    if (MODE == 2) {
        uint4 o;
        __half2* op = reinterpret_cast<__half2*>(&o);
        op[0] = __floats2half2_rn(acc[0], acc[1]);
        op[1] = __floats2half2_rn(acc[2], acc[3]);
        op[2] = __floats2half2_rn(acc[4], acc[5]);
        op[3] = __floats2half2_rn(acc[6], acc[7]);
        *reinterpret_cast<uint4*>(outfp16 + (size_t)node * DHID + c) = o;
    } else {
        __nv_bfloat16 hi8[8], lo8[8];
#pragma unroll
        for (int i = 0; i < 8; i++) {
            float v = fmaxf(acc[i], 0.f);
            __nv_bfloat16 hv = __float2bfloat16(v);
            hi8[i] = hv;
            lo8[i] = __float2bfloat16(v - __bfloat162float(hv));
        }
        *reinterpret_cast<uint4*>(outh + (size_t)node * DHID + c) =
            *reinterpret_cast<const uint4*>(hi8);
        *reinterpret_cast<uint4*>(outl + (size_t)node * DHID + c) =
            *reinterpret_cast<const uint4*>(lo8);
    }
}

// ---------------------------------------------------------------------------
// Edge scoring from fp16 features (one warp per edge, fp32 accumulate).
// ---------------------------------------------------------------------------
__global__ __launch_bounds__(256)
void score_fp16_kernel(const __half* __restrict__ h,
                       const int* __restrict__ src,
                       const int* __restrict__ dst,
                       float* __restrict__ out, int e) {
    unsigned gt = blockIdx.x * blockDim.x + threadIdx.x;
    unsigned ed = gt >> 5;
    const int lane = threadIdx.x & 31;
    if (ed >= (unsigned)e) return;
    const int s = src[ed];
    const int d = dst[ed];
    uint4 su = *(reinterpret_cast<const uint4*>(h + (size_t)s * DHID) + lane);
    uint4 du = *(reinterpret_cast<const uint4*>(h + (size_t)d * DHID) + lane);
    const __half2* sv = reinterpret_cast<const __half2*>(&su);
    const __half2* dv = reinterpret_cast<const __half2*>(&du);
    float acc = 0.0f;
#pragma unroll
    for (int i = 0; i < 4; i++) {
        float2 a = __half22float2(sv[i]);
        float2 b = __half22float2(dv[i]);
        acc = fmaf(a.x, b.x, acc);
        acc = fmaf(a.y, b.y, acc);
    }
#pragma unroll
    for (int off = 16; off > 0; off >>= 1)
        acc += __shfl_xor_sync(0xFFFFFFFFu, acc, off);
    if (lane == 0) out[ed] = 1.0f / (1.0f + expf(-acc));
}

// ---------------------------------------------------------------------------
// Host launcher — CSR build forked onto a side stream
// ---------------------------------------------------------------------------
extern "C" void kernel_launch(void* const* d_in, const int* in_sizes, int n_in,
                              void* d_out, int out_size) {
    const float* x  = (const float*)d_in[0];
    const int*   ei = (const int*)d_in[1];
    const float* W1 = (const float*)d_in[2];
    const float* b1 = (const float*)d_in[3];
    const float* W2 = (const float*)d_in[4];
    const float* b2 = (const float*)d_in[5];
    float* out = (float*)d_out;

    const int N = in_sizes[0] / DIN;
    const int E = in_sizes[1] / 2;
    const int* src = ei;
    const int* dst = ei + E;

    int *p_cnt, *p_rowptr, *p_off, *p_esrc, *p_bsum, *p_boff;
    float *p_dinv, *p_ecoef;
    __half *p_h1, *p_h2, *p_agg2;
    __nv_bfloat16 *p_xh, *p_xl, *p_w1h, *p_w1l, *p_w2h, *p_w2l, *p_a1h, *p_a1l;
    cudaGetSymbolAddress((void**)&p_cnt,    g_cnt);
    cudaGetSymbolAddress((void**)&p_dinv,   g_dinv);
    cudaGetSymbolAddress((void**)&p_rowptr, g_rowptr);
    cudaGetSymbolAddress((void**)&p_off,    g_off);
    cudaGetSymbolAddress((void**)&p_bsum,   g_blocksum);
    cudaGetSymbolAddress((void**)&p_boff,   g_blockoff);
    cudaGetSymbolAddress((void**)&p_esrc,   g_esrc);
    cudaGetSymbolAddress((void**)&p_ecoef,  g_ecoef);
    cudaGetSymbolAddress((void**)&p_xh,     g_xh);
    cudaGetSymbolAddress((void**)&p_xl,     g_xl);
    cudaGetSymbolAddress((void**)&p_w1h,    g_w1h);
    cudaGetSymbolAddress((void**)&p_w1l,    g_w1l);
    cudaGetSymbolAddress((void**)&p_w2h,    g_w2h);
    cudaGetSymbolAddress((void**)&p_w2l,    g_w2l);
    cudaGetSymbolAddress((void**)&p_h1,     g_h1);
    cudaGetSymbolAddress((void**)&p_a1h,    g_a1h);
    cudaGetSymbolAddress((void**)&p_a1l,    g_a1l);
    cudaGetSymbolAddress((void**)&p_h2,     g_h2);
    cudaGetSymbolAddress((void**)&p_agg2,   g_agg2);

    static cudaStream_t s_side = nullptr;
    static cudaEvent_t  s_fork = nullptr, s_join = nullptr;
    if (s_side == nullptr) {
        cudaStreamCreateWithFlags(&s_side, cudaStreamNonBlocking);
        cudaEventCreateWithFlags(&s_fork, cudaEventDisableTiming);
        cudaEventCreateWithFlags(&s_join, cudaEventDisableTiming);
    }

    const int T = 256;

    // ---- fork: CSR build chain on side stream ----
    cudaEventRecord(s_fork, 0);
    cudaStreamWaitEvent(s_side, s_fork, 0);
    zero_cnt_kernel<<<(N + T - 1) / T, T, 0, s_side>>>(p_cnt, N);
    hist_kernel<<<(E + T - 1) / T, T, 0, s_side>>>(p_cnt, dst, E);
    dinv_kernel<<<(N + T - 1) / T, T, 0, s_side>>>(p_cnt, p_dinv, N);
    scan_p1_kernel<<<NB_SCAN, 256, 0, s_side>>>(p_cnt, p_bsum, N);
    scan_p2_kernel<<<1, NB_SCAN, 0, s_side>>>(p_bsum, p_boff, p_rowptr, N);
    scan_p3_kernel<<<NB_SCAN, 256, 0, s_side>>>(p_cnt, p_boff, p_rowptr, p_off, N);
    scatter_kernel<<<(E + T - 1) / T, T, 0, s_side>>>(src, dst, p_dinv, p_off,
                                                      p_esrc, p_ecoef, E);
    cudaEventRecord(s_join, s_side);

    // ---- main stream: splits + GEMM1 ----
    {
        int n4 = N * DIN / 4;
        split_kernel<<<(n4 + T - 1) / T, T>>>(x, p_xh, p_xl, n4);
        int w1n4 = DIN * DHID / 4;
        split_kernel<<<(w1n4 + T - 1) / T, T>>>(W1, p_w1h, p_w1l, w1n4);
        int w2n4 = DHID * DHID / 4;
        split_kernel<<<(w2n4 + T - 1) / T, T>>>(W2, p_w2h, p_w2l, w2n4);
    }
    {
        dim3 grid(DHID / 64, (N + 127) / 128);
        mma_gemm_pre_kernel<<<grid, 256>>>(p_xh, p_xl, p_w1h, p_w1l, p_h1, N, DIN, DHID);
    }

    // ---- join: agg1 needs CSR ----
    cudaStreamWaitEvent(0, s_join, 0);
    agg_csr_kernel<1><<<(N + 7) / 8, 256>>>(p_h1, b1, p_dinv, p_rowptr, p_esrc, p_ecoef,
                                            nullptr, p_a1h, p_a1l, N);

    {
        dim3 grid(DHID / 64, (N + 127) / 128);
        mma_gemm_pre_kernel<<<grid, 256>>>(p_a1h, p_a1l, p_w2h, p_w2l, p_h2, N, DHID, DHID);
    }
    agg_csr_kernel<2><<<(N + 7) / 8, 256>>>(p_h2, b2, p_dinv, p_rowptr, p_esrc, p_ecoef,
                                            p_agg2, nullptr, nullptr, N);

    // ---- edge scoring from fp16 ----
    score_fp16_kernel<<<((unsigned)E * 32 + T - 1) / T, T>>>(p_agg2, src, dst, out, E);
}